// round 13
// baseline (speedup 1.0000x reference)
#include <cuda_runtime.h>
#include <cuda_bf16.h>
#include <math.h>
#include <stdint.h>

// Problem constants
#define BB 2
#define TT 2048
#define EE 512
#define HH 8
#define HD 64
#define MM 64
#define LL 32
#define BH (BB*HH)
#define NCHUNK 16

// Scratch (device globals; no runtime allocation)
__device__ float g_q[BB*TT*EE];          // q = x@Wq + bq (plain [4096][512])
__device__ float g_xr[BB*TT*EE];         // x in frag-A order, tf32-rounded
__device__ float g_xmean[128*EE];        // group means of x (fp32)
__device__ float g_ql[BH*MM*HD];         // landmark q (scaled 0.125)
__device__ float g_kl[BH*MM*HD];         // landmark k
__device__ float g_k64[BH*MM*HD];        // k rows 0..63 per (b,h)
__device__ float g_v64[BH*MM*HD];        // v rows 0..63 per (b,h)
__device__ float g_zB[BH*MM*HD];
__device__ float g_y[BB*TT*EE];          // y in frag-A order, tf32-rounded
__device__ float g_wqkvT[EE*EE];         // w_qkv q-cols in frag-B order, rounded
__device__ float g_wprojT[EE*EE];        // w_proj in frag-B order, rounded
__device__ int   g_gmax[2];              // global max col/row sums (float-as-int)
__device__ int   g_sync0, g_sync1;       // chain dependency counters
__device__ int   g_ydone[32];            // y row-tile completion counters

__device__ __forceinline__ uint32_t tf32r(float x) {
    uint32_t r; asm("cvt.rna.tf32.f32 %0, %1;" : "=r"(r) : "f"(x)); return r;
}
__device__ __forceinline__ float tf32f(float x) {
    return __uint_as_float(tf32r(x));
}
__device__ __forceinline__ float ldcg(const float* p) {
    float v; asm volatile("ld.global.cg.f32 %0, [%1];" : "=f"(v) : "l"(p)); return v;
}
__device__ __forceinline__ uint32_t smem_u32(const void* p) {
    uint32_t a;
    asm("{ .reg .u64 t; cvta.to.shared.u64 t, %1; cvt.u32.u64 %0, t; }" : "=r"(a) : "l"(p));
    return a;
}
__device__ __forceinline__ void cp16(uint32_t s, const void* g) {
    asm volatile("cp.async.cg.shared.global [%0], [%1], 16;" :: "r"(s), "l"(g));
}
#define CP_COMMIT() asm volatile("cp.async.commit_group;" ::: "memory")
#define CP_WAIT(n)  asm volatile("cp.async.wait_group %0;" :: "n"(n) : "memory")

__device__ __forceinline__ void mma_tf32(float* d, const uint32_t* a,
                                         const uint32_t* b, const float* c) {
    asm volatile(
        "mma.sync.aligned.m16n8k8.row.col.f32.tf32.tf32.f32 "
        "{%0,%1,%2,%3}, {%4,%5,%6,%7}, {%8,%9}, {%10,%11,%12,%13};"
        : "=f"(d[0]), "=f"(d[1]), "=f"(d[2]), "=f"(d[3])
        : "r"(a[0]), "r"(a[1]), "r"(a[2]), "r"(a[3]),
          "r"(b[0]), "r"(b[1]),
          "f"(c[0]), "f"(c[1]), "f"(c[2]), "f"(c[3]));
}

// ---------------------------------------------------------------------------
// prep_kernel: blocks 0..511: x chunk -> g_xr (frag-A) + xmean partials;
//              512..575: w_qkv q-cols -> g_wqkvT; 576..639: w_proj -> g_wprojT.
// Re-arms all sync globals each replay.
// ---------------------------------------------------------------------------
__global__ __launch_bounds__(256)
void prep_kernel(const float* __restrict__ x, const float* __restrict__ wqkv,
                 const float* __restrict__ wproj) {
    __shared__ float t[128 * 36];   // >= 32*132
    int bid = blockIdx.x, tid = threadIdx.x;
    if (bid == 0) {
        if (tid == 0) { g_gmax[0] = 0; g_gmax[1] = 0; g_sync0 = 0; g_sync1 = 0; }
        if (tid < 32) g_ydone[tid] = 0;
    }
    if (bid < 512) {
        int ch = bid, rt = ch >> 4, c = ch & 15;
        #pragma unroll
        for (int i = 0; i < 4; i++) {
            int s = tid + i * 256, r = s >> 3, c4 = (s & 7) * 4;
            float4 v = *(const float4*)(x + (size_t)(rt * 128 + r) * 512 + c * 32 + c4);
            t[r * 36 + c4] = v.x; t[r * 36 + c4 + 1] = v.y;
            t[r * 36 + c4 + 2] = v.z; t[r * 36 + c4 + 3] = v.w;
        }
        __syncthreads();
        #pragma unroll
        for (int i = 0; i < 4; i++) {
            int f = tid + i * 256;
            int lane = f & 31, kk = (f >> 5) & 3, mb = f >> 7;
            int grp = lane >> 2, tig = lane & 3;
            int rr = mb * 16 + grp, cc = kk * 8 + tig;
            float4 o;
            o.x = tf32f(t[rr * 36 + cc]);
            o.y = tf32f(t[(rr + 8) * 36 + cc]);
            o.z = tf32f(t[rr * 36 + cc + 4]);
            o.w = tf32f(t[(rr + 8) * 36 + cc + 4]);
            *(float4*)(g_xr + (size_t)ch * 4096 + f * 4) = o;
        }
        if (tid < 128) {
            int gr = tid >> 5, cc = tid & 31;
            float s = 0.f;
            #pragma unroll 8
            for (int i = 0; i < 32; i++) s += t[(gr * 32 + i) * 36 + cc];
            g_xmean[(rt * 4 + gr) * 512 + c * 32 + cc] = s * (1.0f / 32.0f);
        }
    } else {
        const float* w; float* dst; int N, ch;
        if (bid < 576) { w = wqkv; dst = g_wqkvT; N = 1536; ch = bid - 512; }
        else           { w = wproj; dst = g_wprojT; N = 512;  ch = bid - 576; }
        int ntile = ch >> 4, c = ch & 15;
        #pragma unroll
        for (int i = 0; i < 4; i++) {
            int s = tid + i * 256, kr = s >> 5, n4 = (s & 31) * 4;
            float4 v = *(const float4*)(w + (size_t)(c * 32 + kr) * N + ntile * 128 + n4);
            t[kr * 132 + n4] = v.x; t[kr * 132 + n4 + 1] = v.y;
            t[kr * 132 + n4 + 2] = v.z; t[kr * 132 + n4 + 3] = v.w;
        }
        __syncthreads();
        #pragma unroll
        for (int i = 0; i < 8; i++) {
            int f = tid + i * 256;
            int lane = f & 31, kk = (f >> 5) & 3, nb = f >> 7;
            int grp = lane >> 2, tig = lane & 3;
            int nn = nb * 8 + grp, kx = kk * 8 + tig;
            float2 o;
            o.x = tf32f(t[kx * 132 + nn]);
            o.y = tf32f(t[(kx + 4) * 132 + nn]);
            *(float2*)(dst + (size_t)ch * 4096 + f * 2) = o;
        }
    }
}

// ---------------------------------------------------------------------------
// Tensor-core 64x64 matmul on PS-padded smem. C = scale * L @ R' with
// R' = (NEG ? dc*I - R : R); R stored [k][n]. RNDOUT rounds C to tf32.
// ---------------------------------------------------------------------------
#define PS 68
#define PB (64 * PS)

template<bool NEG, bool RNDOUT>
__device__ __forceinline__ void mmtc(float* __restrict__ C,
                                     const float* __restrict__ L,
                                     const float* __restrict__ R,
                                     float dc, float scale) {
    int wid = threadIdx.x >> 5, lane = threadIdx.x & 31;
    int grp = lane >> 2, tig = lane & 3;
    int m0 = (wid & 3) * 16, n0 = (wid >> 2) * 32;

    float acc[4][4];
    #pragma unroll
    for (int nt = 0; nt < 4; nt++)
        #pragma unroll
        for (int r = 0; r < 4; r++) acc[nt][r] = 0.f;

    #pragma unroll
    for (int kk = 0; kk < 64; kk += 8) {
        uint32_t a[4];
        a[0] = __float_as_uint(L[(m0 + grp) * PS + kk + tig]);
        a[1] = __float_as_uint(L[(m0 + grp + 8) * PS + kk + tig]);
        a[2] = __float_as_uint(L[(m0 + grp) * PS + kk + tig + 4]);
        a[3] = __float_as_uint(L[(m0 + grp + 8) * PS + kk + tig + 4]);
        #pragma unroll
        for (int nt = 0; nt < 4; nt++) {
            int n = n0 + nt * 8 + grp;
            float b0v = R[(kk + tig) * PS + n];
            float b1v = R[(kk + tig + 4) * PS + n];
            uint32_t b[2];
            if (NEG) {
                b0v = ((kk + tig) == n ? dc : 0.f) - b0v;
                b1v = ((kk + tig + 4) == n ? dc : 0.f) - b1v;
                b[0] = tf32r(b0v);
                b[1] = tf32r(b1v);
            } else {
                b[0] = __float_as_uint(b0v);
                b[1] = __float_as_uint(b1v);
            }
            mma_tf32(acc[nt], a, b, acc[nt]);
        }
    }

    #pragma unroll
    for (int nt = 0; nt < 4; nt++) {
        int c0 = n0 + nt * 8 + tig * 2;
        float o0 = acc[nt][0] * scale, o1 = acc[nt][1] * scale;
        float o2 = acc[nt][2] * scale, o3 = acc[nt][3] * scale;
        if (RNDOUT) { o0 = tf32f(o0); o1 = tf32f(o1); o2 = tf32f(o2); o3 = tf32f(o3); }
        C[(m0 + grp) * PS + c0]         = o0;
        C[(m0 + grp) * PS + c0 + 1]     = o1;
        C[(m0 + grp + 8) * PS + c0]     = o2;
        C[(m0 + grp + 8) * PS + c0 + 1] = o3;
    }
    __syncthreads();
}

// ---------------------------------------------------------------------------
// Masked row-softmax over a PS-padded 64x64 buffer.
// RND: round probs to tf32 (when they feed an mma directly).
// ---------------------------------------------------------------------------
template<bool RND>
__device__ __forceinline__ void softmax64(float* S) {
    int w = threadIdx.x / 32, lane = threadIdx.x % 32;
    for (int r = 0; r < 8; r++) {
        int i = w * 8 + r;
        float a0 = S[i * PS + lane];
        float a1 = S[i * PS + lane + 32];
        if (lane > i) a0 = -INFINITY;
        if (lane + 32 > i) a1 = -INFINITY;
        float mx = fmaxf(a0, a1);
        for (int o = 16; o > 0; o >>= 1) mx = fmaxf(mx, __shfl_xor_sync(0xffffffffu, mx, o));
        float e0 = expf(a0 - mx), e1 = expf(a1 - mx);
        float sm = e0 + e1;
        for (int o = 16; o > 0; o >>= 1) sm += __shfl_xor_sync(0xffffffffu, sm, o);
        float inv = 1.0f / sm;
        float p0 = e0 * inv, p1 = e1 * inv;
        if (RND) { p0 = tf32f(p0); p1 = tf32f(p1); }
        S[i * PS + lane] = p0;
        S[i * PS + lane + 32] = p1;
    }
    __syncthreads();
}

// ---------------------------------------------------------------------------
// lgemm body: part 0 -> ql/kl from xmean; part 1 -> k64/v64 from x[:64].
// ---------------------------------------------------------------------------
__device__ void lgemm_body(float* sb, int bid, const float* __restrict__ x,
                           const float* __restrict__ wqkv,
                           const float* __restrict__ bqkv) {
    float* As = sb;              // 128*36
    float* Bt = sb + 4608;       // 32*132
    int tid = threadIdx.x;
    int part = bid >> 3, ntb = bid & 7;
    int wid = tid >> 5, lane = tid & 31;
    int wm = (wid >> 2) * 64, wn = (wid & 3) * 32;
    int grp = lane >> 2, tig = lane & 3;
    int nbase = part ? (512 + ntb * 128) : (ntb * 128);

    float acc[4][4][4] = {};

    for (int k0 = 0; k0 < 512; k0 += 32) {
        #pragma unroll
        for (int i = 0; i < 4; i++) {
            int s = tid + i * 256, r = s >> 3, c4 = (s & 7) * 4;
            const float* arow;
            if (part == 0) arow = g_xmean + (size_t)r * 512;
            else           arow = x + ((size_t)((r >> 6) * TT + (r & 63))) * 512;
            float4 v = *(const float4*)(arow + k0 + c4);
            As[r * 36 + c4]     = tf32f(v.x);
            As[r * 36 + c4 + 1] = tf32f(v.y);
            As[r * 36 + c4 + 2] = tf32f(v.z);
            As[r * 36 + c4 + 3] = tf32f(v.w);
        }
        #pragma unroll
        for (int i = 0; i < 4; i++) {
            int s = tid + i * 256, kr = s >> 5, n4 = (s & 31) * 4;
            float4 v = *(const float4*)(wqkv + (size_t)(k0 + kr) * 1536 + nbase + n4);
            Bt[kr * 132 + n4]     = tf32f(v.x);
            Bt[kr * 132 + n4 + 1] = tf32f(v.y);
            Bt[kr * 132 + n4 + 2] = tf32f(v.z);
            Bt[kr * 132 + n4 + 3] = tf32f(v.w);
        }
        __syncthreads();

        #pragma unroll
        for (int kk = 0; kk < 32; kk += 8) {
            uint32_t af[4][4], bf[4][2];
            #pragma unroll
            for (int mt = 0; mt < 4; mt++) {
                int m = wm + mt * 16;
                af[mt][0] = __float_as_uint(As[(m + grp) * 36 + kk + tig]);
                af[mt][1] = __float_as_uint(As[(m + grp + 8) * 36 + kk + tig]);
                af[mt][2] = __float_as_uint(As[(m + grp) * 36 + kk + tig + 4]);
                af[mt][3] = __float_as_uint(As[(m + grp + 8) * 36 + kk + tig + 4]);
            }
            #pragma unroll
            for (int nt = 0; nt < 4; nt++) {
                int n = wn + nt * 8 + grp;
                bf[nt][0] = __float_as_uint(Bt[(kk + tig) * 132 + n]);
                bf[nt][1] = __float_as_uint(Bt[(kk + tig + 4) * 132 + n]);
            }
            #pragma unroll
            for (int mt = 0; mt < 4; mt++)
                #pragma unroll
                for (int nt = 0; nt < 4; nt++)
                    mma_tf32(acc[mt][nt], af[mt], bf[nt], acc[mt][nt]);
        }
        __syncthreads();
    }

    #pragma unroll
    for (int mt = 0; mt < 4; mt++) {
        int row0 = wm + mt * 16 + grp;
        #pragma unroll
        for (int nt = 0; nt < 4; nt++) {
            int nloc0 = ntb * 128 + wn + nt * 8 + tig * 2;
            #pragma unroll
            for (int q = 0; q < 4; q++) {
                int row = row0 + (q >> 1) * 8;
                int nloc = nloc0 + (q & 1);
                float val = acc[mt][nt][q] + bqkv[(part ? 512 : 0) + nloc];
                int b = row >> 6, mj = row & 63;
                int h = nloc >> 6, d = nloc & 63;
                if (part == 0) {
                    if (h < 8) g_ql[((b * 8 + h) * 64 + mj) * 64 + d] = val * 0.125f;
                    else       g_kl[((b * 8 + h - 8) * 64 + mj) * 64 + d] = val;
                } else {
                    if (h < 8) g_k64[((b * 8 + h) * 64 + mj) * 64 + d] = val;
                    else       g_v64[((b * 8 + h - 8) * 64 + mj) * 64 + d] = val;
                }
            }
        }
    }
}

// ---------------------------------------------------------------------------
// pinvAB body: per-bh A-softmax + sums, Bv (hides global-sum barrier),
// Newton-Schulz pinv, zB. All in smem; 6 PB buffers.
// ---------------------------------------------------------------------------
__device__ void pinvab_body(float* sb, int bh) {
    float* As = sb;
    float* Wa = sb + 1 * PB;
    float* Wb = sb + 2 * PB;
    float* Wc = sb + 3 * PB;
    float* Wd = sb + 4 * PB;
    float* Bv = sb + 5 * PB;
    float* red = sb + 6 * PB;   // 128 floats reduction scratch
    int tid = threadIdx.x;

    // ql -> Wa (L layout), kl^T -> Wb (R layout)
    for (int idx = tid; idx < 4096; idx += 256) {
        int j = idx >> 6, d = idx & 63;
        Wa[j * PS + d] = tf32f(ldcg(g_ql + bh * 4096 + idx));
        Wb[d * PS + j] = tf32f(ldcg(g_kl + bh * 4096 + idx));
    }
    __syncthreads();
    mmtc<false, false>(Wc, Wa, Wb, 0.f, 1.0f);   // logits
    softmax64<false>(Wc);                         // fp32 probs

    // As = tf32(probs); col/row sums of fp32 probs
    for (int idx = tid; idx < 4096; idx += 256) {
        int i = idx >> 6, j = idx & 63;
        As[i * PS + j] = tf32f(Wc[i * PS + j]);
    }
    if (tid < 128) {
        int li = tid & 63;
        float s = 0.f;
        if (tid < 64) { for (int i = 0; i < 64; i++) s += Wc[i * PS + li]; }   // col sums
        else          { for (int i = 0; i < 64; i++) s += Wc[li * PS + i]; }   // row sums
        red[tid] = s;
    }
    __syncthreads();
    if (tid == 0) {
        float cm = red[0], rm = red[64];
        for (int i = 1; i < 64; i++) { cm = fmaxf(cm, red[i]); rm = fmaxf(rm, red[64 + i]); }
        atomicMax(&g_gmax[0], __float_as_int(cm));
        atomicMax(&g_gmax[1], __float_as_int(rm));
        __threadfence();
        atomicAdd(&g_sync1, 1);
    }

    // Bv (independent of global max; hides the barrier)
    for (int idx = tid; idx < 4096; idx += 256) {
        int j = idx >> 6, d = idx & 63;
        Wb[d * PS + j] = tf32f(ldcg(g_k64 + bh * 4096 + idx));
    }
    __syncthreads();
    mmtc<false, false>(Wc, Wa, Wb, 0.f, 1.0f);   // logits (ql @ k64^T)
    softmax64<true>(Wc);                          // probs rounded
    for (int idx = tid; idx < 4096; idx += 256) {
        int j = idx >> 6, d = idx & 63;
        Wb[j * PS + d] = tf32f(ldcg(g_v64 + bh * 4096 + idx));
    }
    __syncthreads();
    mmtc<false, false>(Bv, Wc, Wb, 0.f, 1.0f);   // Bv = P @ v (fp32)

    // Global-max barrier
    if (tid == 0) {
        while (*((volatile int*)&g_sync1) != 16) { }
        __threadfence();
        float cm = __int_as_float(*((volatile int*)&g_gmax[0]));
        float rm = __int_as_float(*((volatile int*)&g_gmax[1]));
        red[0] = 1.0f / (cm * rm);
    }
    __syncthreads();
    float inv = red[0];

    // z0 = A^T * inv
    for (int idx = tid; idx < 4096; idx += 256) {
        int i = idx >> 6, j = idx & 63;
        Wa[i * PS + j] = tf32f(As[j * PS + i] * inv);
    }
    __syncthreads();

    float* z = Wa;
    float* x = Wb;
    for (int it = 0; it < 6; it++) {
        mmtc<false, true>(x,  As, z,  0.f,  1.0f);
        mmtc<true,  true>(Wc, x,  x,  7.f,  1.0f);
        mmtc<true,  true>(Wd, x,  Wc, 15.f, 1.0f);
        mmtc<true,  true>(x,  z,  Wd, 13.f, 0.25f);
        float* tmp = z; z = x; x = tmp;
    }

    // zB = z @ round(Bv)
    for (int idx = tid; idx < 4096; idx += 256) {
        int i = idx >> 6, j = idx & 63;
        x[i * PS + j] = tf32f(Bv[i * PS + j]);
    }
    __syncthreads();
    mmtc<false, false>(Wc, z, x, 0.f, 1.0f);

    for (int idx = tid; idx < 4096; idx += 256) {
        int i = idx >> 6, j = idx & 63;
        g_zB[bh * 4096 + idx] = Wc[i * PS + j];
    }
}

// ---------------------------------------------------------------------------
// gemm0 body: g_xr @ g_wqkvT -> g_q (Nd=512), frag-order, cp.async 3-stage.
// ---------------------------------------------------------------------------
__device__ void gemm0_body(float* sm, int bx, int by, const float* __restrict__ bias) {
    uint32_t sbase = smem_u32(sm);
    int tid = threadIdx.x, wid = tid >> 5, lane = tid & 31;
    int wmb = (wid >> 2) * 4;
    int wnb = (wid & 3) * 4;
    int grp = lane >> 2, tig = lane & 3;

    const float* Abase = g_xr + (size_t)by * 16 * 4096;
    const float* Bbase = g_wqkvT + (size_t)bx * 16 * 4096;

    float acc[4][4][4];
    #pragma unroll
    for (int mt = 0; mt < 4; mt++)
        #pragma unroll
        for (int nt = 0; nt < 4; nt++)
            #pragma unroll
            for (int r = 0; r < 4; r++) acc[mt][nt][r] = 0.f;

    auto load_chunk = [&](int c, int s) {
        uint32_t a_s = sbase + (uint32_t)(s * 4096) * 4;
        uint32_t b_s = sbase + (uint32_t)((3 + s) * 4096) * 4;
        const float* ag = Abase + c * 4096;
        const float* bg = Bbase + c * 4096;
        #pragma unroll
        for (int i = 0; i < 4; i++) {
            int o = (tid + i * 256) * 4;
            cp16(a_s + o * 4, ag + o);
            cp16(b_s + o * 4, bg + o);
        }
    };

    load_chunk(0, 0); CP_COMMIT();
    load_chunk(1, 1); CP_COMMIT();

    int s = 0;
    for (int c = 0; c < NCHUNK; c++) {
        CP_WAIT(1);
        __syncthreads();
        if (c + 2 < NCHUNK) load_chunk(c + 2, (s + 2) % 3);
        CP_COMMIT();

        const float4* As4 = (const float4*)(sm + s * 4096);
        const float2* Bs2 = (const float2*)(sm + (3 + s) * 4096);

        #pragma unroll
        for (int kk = 0; kk < 4; kk++) {
            float4 af[4]; float2 bf[4];
            #pragma unroll
            for (int mt = 0; mt < 4; mt++)
                af[mt] = As4[((wmb + mt) * 4 + kk) * 32 + lane];
            #pragma unroll
            for (int nt = 0; nt < 4; nt++)
                bf[nt] = Bs2[((wnb + nt) * 4 + kk) * 32 + lane];
            #pragma unroll
            for (int mt = 0; mt < 4; mt++)
                #pragma unroll
                for (int nt = 0; nt < 4; nt++)
                    mma_tf32(acc[mt][nt], (const uint32_t*)&af[mt],
                             (const uint32_t*)&bf[nt], acc[mt][nt]);
        }
        s = (s + 1) % 3;
    }

    #pragma unroll
    for (int mt = 0; mt < 4; mt++) {
        int row0 = by * 128 + (wmb + mt) * 16 + grp;
        #pragma unroll
        for (int nt = 0; nt < 4; nt++) {
            int col0 = bx * 128 + (wnb + nt) * 8 + tig * 2;
            float b0 = bias[col0], b1 = bias[col0 + 1];
            float2 o0 = make_float2(acc[mt][nt][0] + b0, acc[mt][nt][1] + b1);
            float2 o1 = make_float2(acc[mt][nt][2] + b0, acc[mt][nt][3] + b1);
            *(float2*)(g_q + (size_t)row0 * EE + col0) = o0;
            *(float2*)(g_q + (size_t)(row0 + 8) * EE + col0) = o1;
        }
    }
}

// ---------------------------------------------------------------------------
// mega_kernel: grid 160.
//   bids 0..15   : lgemm -> sync0++
//   bids 16..31  : wait sync0==16 -> pinvAB (A + Bv + NS + zB)
//   bids 32..159 : gemm0 (independent; overlaps the chain)
// ---------------------------------------------------------------------------
__global__ __launch_bounds__(256)
void mega_kernel(const float* __restrict__ x, const float* __restrict__ wqkv,
                 const float* __restrict__ bqkv) {
    extern __shared__ float sb[];
    int bid = blockIdx.x, tid = threadIdx.x;

    if (bid < 16) {
        lgemm_body(sb, bid, x, wqkv, bqkv);
        __threadfence();
        __syncthreads();
        if (tid == 0) atomicAdd(&g_sync0, 1);
    } else if (bid < 32) {
        if (tid == 0) { while (*((volatile int*)&g_sync0) != 16) { } }
        __syncthreads();
        pinvab_body(sb, bid - 16);
    } else {
        int gb = bid - 32;
        gemm0_body(sb, gb & 3, gb >> 2, bqkv);
    }
}
#define MEGA_SMEM ((6 * PB + 128) * 4)   // 104960 B (pinvAB is the max user)

// ---------------------------------------------------------------------------
// FYG kernel: grid 640.
//   bids 0..511  : FY (y tile) -> per-row-tile counter++
//   bids 512..639: gemm1 (waits for its y row-tile: 16 FY blocks)
// ---------------------------------------------------------------------------
__global__ __launch_bounds__(256)
void FYG_kernel(const float* __restrict__ bias, float* __restrict__ Cout) {
    extern __shared__ float sb[];
    int bid = blockIdx.x, tid = threadIdx.x;

    if (bid < 512) {
        // ---- FY body ----
        float* ks = sb;
        float* qs = sb + PB;
        float* Ss = sb + 2 * PB;
        int tt = bid & 31, bh = bid >> 5;
        int b = bh / HH, h = bh % HH;

        for (int idx = tid; idx < 4096; idx += 256) {
            int j = idx >> 6, d = idx & 63;
            ks[d * PS + j] = tf32f(g_kl[bh * 4096 + idx]);
        }
        for (int idx = tid; idx < 4096; idx += 256) {
            int r = idx >> 6, d = idx & 63;
            qs[r * PS + d] = tf32f(g_q[((size_t)(b * TT + tt * 64 + r)) * EE + h * HD + d] * 0.125f);
        }
        __syncthreads();

        mmtc<false, false>(Ss, qs, ks, 0.f, 1.0f);

        int w = tid / 32, lane = tid % 32;
        for (int r = 0; r < 8; r++) {
            int row = w * 8 + r;
            int t = tt * 64 + row;
            float a0 = Ss[row * PS + lane];
            float a1 = Ss[row * PS + lane + 32];
            if (lane > t) a0 = -INFINITY;
            if (lane + 32 > t) a1 = -INFINITY;
            float mx = fmaxf(a0, a1);
            for (int o = 16; o > 0; o >>= 1) mx = fmaxf(mx, __shfl_xor_sync(0xffffffffu, mx, o));
            float e0 = expf(a0 - mx), e1 = expf(a1 - mx);
            float sm = e0 + e1;
            for (int o = 16; o > 0; o >>= 1) sm += __shfl_xor_sync(0xffffffffu, sm, o);
            float inv = 1.0f / sm;
            Ss[row * PS + lane] = tf32f(e0 * inv);
            Ss[row * PS + lane + 32] = tf32f(e1 * inv);
        }
        __syncthreads();

        for (int idx = tid; idx < 4096; idx += 256) {
            int m = idx >> 6, d = idx & 63;
            ks[m * PS + d] = tf32f(g_zB[bh * 4096 + idx]);
        }
        __syncthreads();

        mmtc<false, false>(qs, Ss, ks, 0.f, 1.0f);

        int rt = (b * TT + tt * 64) >> 7;
        int mb0 = (tt & 1) * 4;
        #pragma unroll
        for (int c_off = 0; c_off < 2; c_off++) {
            int cch = h * 2 + c_off;
            size_t base_f4 = ((size_t)(rt * 16 + cch)) * 1024 + mb0 * 128;
            #pragma unroll
            for (int i = 0; i < 2; i++) {
                int u = tid + i * 256;
                int lane2 = u & 31, kk = (u >> 5) & 3, mbr = u >> 7;
                int grp = lane2 >> 2, tig = lane2 & 3;
                int rl = mbr * 16 + grp;
                int dd = c_off * 32 + kk * 8 + tig;
                float4 o;
                o.x = tf32f(qs[rl * PS + dd]);
                o.y = tf32f(qs[(rl + 8) * PS + dd]);
                o.z = tf32f(qs[rl * PS + dd + 4]);
                o.w = tf32f(qs[(rl + 8) * PS + dd + 4]);
                *(float4*)(g_y + (base_f4 + u) * 4) = o;
            }
        }
        __threadfence();
        __syncthreads();
        if (tid == 0) atomicAdd(&g_ydone[rt], 1);
    } else {
        // ---- gemm1 body ----
        int gb = bid - 512;
        int by = gb >> 2, bx = gb & 3;
        if (tid == 0) { while (*((volatile int*)&g_ydone[by]) != 16) { } }
        __syncthreads();

        float* sm = sb;
        uint32_t sbase = smem_u32(sm);
        int wid = tid >> 5, lane = tid & 31;
        int wmb = (wid >> 2) * 4;
        int wnb = (wid & 3) * 4;
        int grp = lane >> 2, tig = lane & 3;

        const float* Abase = g_y + (size_t)by * 16 * 4096;
        const float* Bbase = g_wprojT + (size_t)bx * 16 * 4096;

        float acc[4][4][4];
        #pragma unroll
        for (int mt = 0; mt < 4; mt++)
            #pragma unroll
            for (int nt = 0; nt < 4; nt++)
                #pragma unroll
                for (int r = 0; r < 4; r++) acc[mt][nt][r] = 0.f;

        auto load_chunk = [&](int c, int s) {
            uint32_t a_s = sbase + (uint32_t)(s * 4096) * 4;
            uint32_t b_s = sbase + (uint32_t)((3 + s) * 4096) * 4;
            const float* ag = Abase + c * 4096;
            const float* bg = Bbase + c * 4096;
            #pragma unroll
            for (int i = 0; i < 4; i++) {
                int o = (tid + i * 256) * 4;
                cp16(a_s + o * 4, ag + o);
                cp16(b_s + o * 4, bg + o);
            }
        };

        load_chunk(0, 0); CP_COMMIT();
        load_chunk(1, 1); CP_COMMIT();

        int s = 0;
        for (int c = 0; c < NCHUNK; c++) {
            CP_WAIT(1);
            __syncthreads();
            if (c + 2 < NCHUNK) load_chunk(c + 2, (s + 2) % 3);
            CP_COMMIT();

            const float4* As4 = (const float4*)(sm + s * 4096);
            const float2* Bs2 = (const float2*)(sm + (3 + s) * 4096);

            #pragma unroll
            for (int kk = 0; kk < 4; kk++) {
                float4 af[4]; float2 bf[4];
                #pragma unroll
                for (int mt = 0; mt < 4; mt++)
                    af[mt] = As4[((wmb + mt) * 4 + kk) * 32 + lane];
                #pragma unroll
                for (int nt = 0; nt < 4; nt++)
                    bf[nt] = Bs2[((wnb + nt) * 4 + kk) * 32 + lane];
                #pragma unroll
                for (int mt = 0; mt < 4; mt++)
                    #pragma unroll
                    for (int nt = 0; nt < 4; nt++)
                        mma_tf32(acc[mt][nt], (const uint32_t*)&af[mt],
                                 (const uint32_t*)&bf[nt], acc[mt][nt]);
            }
            s = (s + 1) % 3;
        }

        #pragma unroll
        for (int mt = 0; mt < 4; mt++) {
            int row0 = by * 128 + (wmb + mt) * 16 + grp;
            #pragma unroll
            for (int nt = 0; nt < 4; nt++) {
                int col0 = bx * 128 + (wnb + nt) * 8 + tig * 2;
                float b0 = bias[col0], b1 = bias[col0 + 1];
                float2 o0 = make_float2(acc[mt][nt][0] + b0, acc[mt][nt][1] + b1);
                float2 o1 = make_float2(acc[mt][nt][2] + b0, acc[mt][nt][3] + b1);
                *(float2*)(Cout + (size_t)row0 * EE + col0) = o0;
                *(float2*)(Cout + (size_t)(row0 + 8) * EE + col0) = o1;
            }
        }
    }
}
#define FYG_SMEM (6 * 4096 * 4)   // 98304 B (gemm1 is the max user)

// ---------------------------------------------------------------------------
extern "C" void kernel_launch(void* const* d_in, const int* in_sizes, int n_in,
                              void* d_out, int out_size) {
    const float* x      = (const float*)d_in[0];
    const float* w_qkv  = (const float*)d_in[1];
    const float* b_qkv  = (const float*)d_in[2];
    const float* w_proj = (const float*)d_in[3];
    const float* b_proj = (const float*)d_in[4];
    float* out = (float*)d_out;

    cudaFuncSetAttribute(mega_kernel,
                         cudaFuncAttributeMaxDynamicSharedMemorySize, MEGA_SMEM);
    cudaFuncSetAttribute(FYG_kernel,
                         cudaFuncAttributeMaxDynamicSharedMemorySize, FYG_SMEM);

    // 0. permute+round x (+ xmean), weights; re-arm sync counters
    prep_kernel<<<640, 256>>>(x, w_qkv, w_proj);
    // 1. mega: [lgemm -> pinvAB(A,Bv,NS,zB)] chain  ||  gemm0
    mega_kernel<<<160, 256, MEGA_SMEM>>>(x, w_qkv, b_qkv);
    // 2. FY (y tiles) || gemm1 (out), linked by row-tile counters
    FYG_kernel<<<640, 256, FYG_SMEM>>>(b_proj, out);
}

// round 14
// speedup vs baseline: 1.0986x; 1.0986x over previous
#include <cuda_runtime.h>
#include <cuda_bf16.h>
#include <math.h>
#include <stdint.h>

// Problem constants
#define BB 2
#define TT 2048
#define EE 512
#define HH 8
#define HD 64
#define MM 64
#define LL 32
#define BH (BB*HH)
#define NCHUNK 16

// Scratch (device globals; no runtime allocation)
__device__ float g_q[BB*TT*EE];          // q = x@Wq + bq (plain [4096][512])
__device__ float g_xr[BB*TT*EE];         // x in frag-A order, tf32-rounded
__device__ float g_xmean[128*EE];        // group means of x (fp32)
__device__ float g_ql[BH*MM*HD];         // landmark q (scaled 0.125)
__device__ float g_kl[BH*MM*HD];         // landmark k
__device__ float g_k64[BH*MM*HD];        // k rows 0..63 per (b,h)
__device__ float g_v64[BH*MM*HD];        // v rows 0..63 per (b,h)
__device__ float g_A[BH*MM*MM];
__device__ float g_Bv[BH*MM*HD];
__device__ float g_zB[BH*MM*HD];
__device__ float g_y[BB*TT*EE];          // y in frag-A order, tf32-rounded
__device__ float g_wqkvT[EE*EE];         // w_qkv q-cols in frag-B order, rounded
__device__ float g_wprojT[EE*EE];        // w_proj in frag-B order, rounded
__device__ int   g_gmax[2];              // global max col/row sums (float-as-int)
__device__ int   g_sync0;                // chain dependency counter

__device__ __forceinline__ uint32_t tf32r(float x) {
    uint32_t r; asm("cvt.rna.tf32.f32 %0, %1;" : "=r"(r) : "f"(x)); return r;
}
__device__ __forceinline__ float tf32f(float x) {
    return __uint_as_float(tf32r(x));
}
__device__ __forceinline__ float ldcg(const float* p) {
    float v; asm volatile("ld.global.cg.f32 %0, [%1];" : "=f"(v) : "l"(p)); return v;
}
__device__ __forceinline__ uint32_t smem_u32(const void* p) {
    uint32_t a;
    asm("{ .reg .u64 t; cvta.to.shared.u64 t, %1; cvt.u32.u64 %0, t; }" : "=r"(a) : "l"(p));
    return a;
}
__device__ __forceinline__ void cp16(uint32_t s, const void* g) {
    asm volatile("cp.async.cg.shared.global [%0], [%1], 16;" :: "r"(s), "l"(g));
}
#define CP_COMMIT() asm volatile("cp.async.commit_group;" ::: "memory")
#define CP_WAIT(n)  asm volatile("cp.async.wait_group %0;" :: "n"(n) : "memory")

__device__ __forceinline__ void mma_tf32(float* d, const uint32_t* a,
                                         const uint32_t* b, const float* c) {
    asm volatile(
        "mma.sync.aligned.m16n8k8.row.col.f32.tf32.tf32.f32 "
        "{%0,%1,%2,%3}, {%4,%5,%6,%7}, {%8,%9}, {%10,%11,%12,%13};"
        : "=f"(d[0]), "=f"(d[1]), "=f"(d[2]), "=f"(d[3])
        : "r"(a[0]), "r"(a[1]), "r"(a[2]), "r"(a[3]),
          "r"(b[0]), "r"(b[1]),
          "f"(c[0]), "f"(c[1]), "f"(c[2]), "f"(c[3]));
}

// ---------------------------------------------------------------------------
// prep_kernel: blocks 0..511: x chunk -> g_xr (frag-A) + xmean partials;
//              512..575: w_qkv q-cols -> g_wqkvT; 576..639: w_proj -> g_wprojT.
// Re-arms sync globals each replay.
// ---------------------------------------------------------------------------
__global__ __launch_bounds__(256)
void prep_kernel(const float* __restrict__ x, const float* __restrict__ wqkv,
                 const float* __restrict__ wproj) {
    __shared__ float t[128 * 36];   // >= 32*132
    int bid = blockIdx.x, tid = threadIdx.x;
    if (bid == 0 && tid == 0) {
        g_gmax[0] = 0; g_gmax[1] = 0; g_sync0 = 0;
    }
    if (bid < 512) {
        int ch = bid, rt = ch >> 4, c = ch & 15;
        #pragma unroll
        for (int i = 0; i < 4; i++) {
            int s = tid + i * 256, r = s >> 3, c4 = (s & 7) * 4;
            float4 v = *(const float4*)(x + (size_t)(rt * 128 + r) * 512 + c * 32 + c4);
            t[r * 36 + c4] = v.x; t[r * 36 + c4 + 1] = v.y;
            t[r * 36 + c4 + 2] = v.z; t[r * 36 + c4 + 3] = v.w;
        }
        __syncthreads();
        #pragma unroll
        for (int i = 0; i < 4; i++) {
            int f = tid + i * 256;
            int lane = f & 31, kk = (f >> 5) & 3, mb = f >> 7;
            int grp = lane >> 2, tig = lane & 3;
            int rr = mb * 16 + grp, cc = kk * 8 + tig;
            float4 o;
            o.x = tf32f(t[rr * 36 + cc]);
            o.y = tf32f(t[(rr + 8) * 36 + cc]);
            o.z = tf32f(t[rr * 36 + cc + 4]);
            o.w = tf32f(t[(rr + 8) * 36 + cc + 4]);
            *(float4*)(g_xr + (size_t)ch * 4096 + f * 4) = o;
        }
        if (tid < 128) {
            int gr = tid >> 5, cc = tid & 31;
            float s = 0.f;
            #pragma unroll 8
            for (int i = 0; i < 32; i++) s += t[(gr * 32 + i) * 36 + cc];
            g_xmean[(rt * 4 + gr) * 512 + c * 32 + cc] = s * (1.0f / 32.0f);
        }
    } else {
        const float* w; float* dst; int N, ch;
        if (bid < 576) { w = wqkv; dst = g_wqkvT; N = 1536; ch = bid - 512; }
        else           { w = wproj; dst = g_wprojT; N = 512;  ch = bid - 576; }
        int ntile = ch >> 4, c = ch & 15;
        #pragma unroll
        for (int i = 0; i < 4; i++) {
            int s = tid + i * 256, kr = s >> 5, n4 = (s & 31) * 4;
            float4 v = *(const float4*)(w + (size_t)(c * 32 + kr) * N + ntile * 128 + n4);
            t[kr * 132 + n4] = v.x; t[kr * 132 + n4 + 1] = v.y;
            t[kr * 132 + n4 + 2] = v.z; t[kr * 132 + n4 + 3] = v.w;
        }
        __syncthreads();
        #pragma unroll
        for (int i = 0; i < 8; i++) {
            int f = tid + i * 256;
            int lane = f & 31, kk = (f >> 5) & 3, nb = f >> 7;
            int grp = lane >> 2, tig = lane & 3;
            int nn = nb * 8 + grp, kx = kk * 8 + tig;
            float2 o;
            o.x = tf32f(t[kx * 132 + nn]);
            o.y = tf32f(t[(kx + 4) * 132 + nn]);
            *(float2*)(dst + (size_t)ch * 4096 + f * 2) = o;
        }
    }
}

// ---------------------------------------------------------------------------
// Tensor-core 64x64 matmul on PS-padded smem, 256 threads (8 warps).
// ---------------------------------------------------------------------------
#define PS 68
#define PB (64 * PS)

template<bool NEG, bool RNDOUT>
__device__ __forceinline__ void mmtc(float* __restrict__ C,
                                     const float* __restrict__ L,
                                     const float* __restrict__ R,
                                     float dc, float scale) {
    int wid = threadIdx.x >> 5, lane = threadIdx.x & 31;
    int grp = lane >> 2, tig = lane & 3;
    int m0 = (wid & 3) * 16, n0 = (wid >> 2) * 32;

    float acc[4][4];
    #pragma unroll
    for (int nt = 0; nt < 4; nt++)
        #pragma unroll
        for (int r = 0; r < 4; r++) acc[nt][r] = 0.f;

    #pragma unroll
    for (int kk = 0; kk < 64; kk += 8) {
        uint32_t a[4];
        a[0] = __float_as_uint(L[(m0 + grp) * PS + kk + tig]);
        a[1] = __float_as_uint(L[(m0 + grp + 8) * PS + kk + tig]);
        a[2] = __float_as_uint(L[(m0 + grp) * PS + kk + tig + 4]);
        a[3] = __float_as_uint(L[(m0 + grp + 8) * PS + kk + tig + 4]);
        #pragma unroll
        for (int nt = 0; nt < 4; nt++) {
            int n = n0 + nt * 8 + grp;
            float b0v = R[(kk + tig) * PS + n];
            float b1v = R[(kk + tig + 4) * PS + n];
            uint32_t b[2];
            if (NEG) {
                b0v = ((kk + tig) == n ? dc : 0.f) - b0v;
                b1v = ((kk + tig + 4) == n ? dc : 0.f) - b1v;
                b[0] = tf32r(b0v);
                b[1] = tf32r(b1v);
            } else {
                b[0] = __float_as_uint(b0v);
                b[1] = __float_as_uint(b1v);
            }
            mma_tf32(acc[nt], a, b, acc[nt]);
        }
    }

    #pragma unroll
    for (int nt = 0; nt < 4; nt++) {
        int c0 = n0 + nt * 8 + tig * 2;
        float o0 = acc[nt][0] * scale, o1 = acc[nt][1] * scale;
        float o2 = acc[nt][2] * scale, o3 = acc[nt][3] * scale;
        if (RNDOUT) { o0 = tf32f(o0); o1 = tf32f(o1); o2 = tf32f(o2); o3 = tf32f(o3); }
        C[(m0 + grp) * PS + c0]         = o0;
        C[(m0 + grp) * PS + c0 + 1]     = o1;
        C[(m0 + grp + 8) * PS + c0]     = o2;
        C[(m0 + grp + 8) * PS + c0 + 1] = o3;
    }
    __syncthreads();
}

// ---------------------------------------------------------------------------
// Wide tensor-core 64x64 matmul: 512 threads (16 warps), each warp 16x16.
// Better latency hiding (4 warps/SMSP) for the serial Newton-Schulz chain.
// ---------------------------------------------------------------------------
template<bool NEG, bool RNDOUT>
__device__ __forceinline__ void mmtc512(float* __restrict__ C,
                                        const float* __restrict__ L,
                                        const float* __restrict__ R,
                                        float dc, float scale) {
    int wid = threadIdx.x >> 5, lane = threadIdx.x & 31;
    int grp = lane >> 2, tig = lane & 3;
    int m0 = (wid & 3) * 16, n0 = (wid >> 2) * 16;

    float acc[2][4];
    #pragma unroll
    for (int nt = 0; nt < 2; nt++)
        #pragma unroll
        for (int r = 0; r < 4; r++) acc[nt][r] = 0.f;

    #pragma unroll
    for (int kk = 0; kk < 64; kk += 8) {
        uint32_t a[4];
        a[0] = __float_as_uint(L[(m0 + grp) * PS + kk + tig]);
        a[1] = __float_as_uint(L[(m0 + grp + 8) * PS + kk + tig]);
        a[2] = __float_as_uint(L[(m0 + grp) * PS + kk + tig + 4]);
        a[3] = __float_as_uint(L[(m0 + grp + 8) * PS + kk + tig + 4]);
        #pragma unroll
        for (int nt = 0; nt < 2; nt++) {
            int n = n0 + nt * 8 + grp;
            float b0v = R[(kk + tig) * PS + n];
            float b1v = R[(kk + tig + 4) * PS + n];
            uint32_t b[2];
            if (NEG) {
                b0v = ((kk + tig) == n ? dc : 0.f) - b0v;
                b1v = ((kk + tig + 4) == n ? dc : 0.f) - b1v;
                b[0] = tf32r(b0v);
                b[1] = tf32r(b1v);
            } else {
                b[0] = __float_as_uint(b0v);
                b[1] = __float_as_uint(b1v);
            }
            mma_tf32(acc[nt], a, b, acc[nt]);
        }
    }

    #pragma unroll
    for (int nt = 0; nt < 2; nt++) {
        int c0 = n0 + nt * 8 + tig * 2;
        float o0 = acc[nt][0] * scale, o1 = acc[nt][1] * scale;
        float o2 = acc[nt][2] * scale, o3 = acc[nt][3] * scale;
        if (RNDOUT) { o0 = tf32f(o0); o1 = tf32f(o1); o2 = tf32f(o2); o3 = tf32f(o3); }
        C[(m0 + grp) * PS + c0]         = o0;
        C[(m0 + grp) * PS + c0 + 1]     = o1;
        C[(m0 + grp + 8) * PS + c0]     = o2;
        C[(m0 + grp + 8) * PS + c0 + 1] = o3;
    }
    __syncthreads();
}

// ---------------------------------------------------------------------------
// lgemm body: part 0 -> ql/kl from xmean; part 1 -> k64/v64 from x[:64].
// ---------------------------------------------------------------------------
__device__ void lgemm_body(float* sb, int bid, const float* __restrict__ x,
                           const float* __restrict__ wqkv,
                           const float* __restrict__ bqkv) {
    float* As = sb;              // 128*36
    float* Bt = sb + 4608;       // 32*132
    int tid = threadIdx.x;
    int part = bid >> 3, ntb = bid & 7;
    int wid = tid >> 5, lane = tid & 31;
    int wm = (wid >> 2) * 64, wn = (wid & 3) * 32;
    int grp = lane >> 2, tig = lane & 3;
    int nbase = part ? (512 + ntb * 128) : (ntb * 128);

    float acc[4][4][4] = {};

    for (int k0 = 0; k0 < 512; k0 += 32) {
        #pragma unroll
        for (int i = 0; i < 4; i++) {
            int s = tid + i * 256, r = s >> 3, c4 = (s & 7) * 4;
            const float* arow;
            if (part == 0) arow = g_xmean + (size_t)r * 512;
            else           arow = x + ((size_t)((r >> 6) * TT + (r & 63))) * 512;
            float4 v = *(const float4*)(arow + k0 + c4);
            As[r * 36 + c4]     = tf32f(v.x);
            As[r * 36 + c4 + 1] = tf32f(v.y);
            As[r * 36 + c4 + 2] = tf32f(v.z);
            As[r * 36 + c4 + 3] = tf32f(v.w);
        }
        #pragma unroll
        for (int i = 0; i < 4; i++) {
            int s = tid + i * 256, kr = s >> 5, n4 = (s & 31) * 4;
            float4 v = *(const float4*)(wqkv + (size_t)(k0 + kr) * 1536 + nbase + n4);
            Bt[kr * 132 + n4]     = tf32f(v.x);
            Bt[kr * 132 + n4 + 1] = tf32f(v.y);
            Bt[kr * 132 + n4 + 2] = tf32f(v.z);
            Bt[kr * 132 + n4 + 3] = tf32f(v.w);
        }
        __syncthreads();

        #pragma unroll
        for (int kk = 0; kk < 32; kk += 8) {
            uint32_t af[4][4], bf[4][2];
            #pragma unroll
            for (int mt = 0; mt < 4; mt++) {
                int m = wm + mt * 16;
                af[mt][0] = __float_as_uint(As[(m + grp) * 36 + kk + tig]);
                af[mt][1] = __float_as_uint(As[(m + grp + 8) * 36 + kk + tig]);
                af[mt][2] = __float_as_uint(As[(m + grp) * 36 + kk + tig + 4]);
                af[mt][3] = __float_as_uint(As[(m + grp + 8) * 36 + kk + tig + 4]);
            }
            #pragma unroll
            for (int nt = 0; nt < 4; nt++) {
                int n = wn + nt * 8 + grp;
                bf[nt][0] = __float_as_uint(Bt[(kk + tig) * 132 + n]);
                bf[nt][1] = __float_as_uint(Bt[(kk + tig + 4) * 132 + n]);
            }
            #pragma unroll
            for (int mt = 0; mt < 4; mt++)
                #pragma unroll
                for (int nt = 0; nt < 4; nt++)
                    mma_tf32(acc[mt][nt], af[mt], bf[nt], acc[mt][nt]);
        }
        __syncthreads();
    }

    #pragma unroll
    for (int mt = 0; mt < 4; mt++) {
        int row0 = wm + mt * 16 + grp;
        #pragma unroll
        for (int nt = 0; nt < 4; nt++) {
            int nloc0 = ntb * 128 + wn + nt * 8 + tig * 2;
            #pragma unroll
            for (int q = 0; q < 4; q++) {
                int row = row0 + (q >> 1) * 8;
                int nloc = nloc0 + (q & 1);
                float val = acc[mt][nt][q] + bqkv[(part ? 512 : 0) + nloc];
                int b = row >> 6, mj = row & 63;
                int h = nloc >> 6, d = nloc & 63;
                if (part == 0) {
                    if (h < 8) g_ql[((b * 8 + h) * 64 + mj) * 64 + d] = val * 0.125f;
                    else       g_kl[((b * 8 + h - 8) * 64 + mj) * 64 + d] = val;
                } else {
                    if (h < 8) g_k64[((b * 8 + h) * 64 + mj) * 64 + d] = val;
                    else       g_v64[((b * 8 + h - 8) * 64 + mj) * 64 + d] = val;
                }
            }
        }
    }
}

// ---------------------------------------------------------------------------
// AB body: part 0 -> A softmax + global sum maxima; part 1 -> Bv.
// ---------------------------------------------------------------------------
__device__ void ab_body(float* sb, int part, int bh) {
    float* qs = sb;
    float* ks = sb + PB;
    float* Ss = sb + 2 * PB;
    float* cbuf = sb + 3 * PB;
    float* rbuf = cbuf + 64;
    int tid = threadIdx.x;

    for (int idx = tid; idx < 4096; idx += 256) {
        qs[(idx >> 6) * PS + (idx & 63)] = tf32f(ldcg(g_ql + bh * 4096 + idx));
    }
    const float* kn = (part == 0) ? g_kl : g_k64;
    for (int idx = tid; idx < 4096; idx += 256) {
        int j = idx >> 6, d = idx & 63;
        ks[d * PS + j] = tf32f(ldcg(kn + bh * 4096 + idx));
    }
    __syncthreads();

    mmtc<false, false>(Ss, qs, ks, 0.f, 1.0f);

    int w = tid / 32, lane = tid % 32;
    for (int r = 0; r < 8; r++) {
        int i = w * 8 + r;
        float a0 = Ss[i * PS + lane];
        float a1 = Ss[i * PS + lane + 32];
        if (lane > i) a0 = -INFINITY;
        if (lane + 32 > i) a1 = -INFINITY;
        float mx = fmaxf(a0, a1);
        for (int o = 16; o > 0; o >>= 1) mx = fmaxf(mx, __shfl_xor_sync(0xffffffffu, mx, o));
        float e0 = expf(a0 - mx), e1 = expf(a1 - mx);
        float sm = e0 + e1;
        for (int o = 16; o > 0; o >>= 1) sm += __shfl_xor_sync(0xffffffffu, sm, o);
        float inv = 1.0f / sm;
        float p0 = e0 * inv, p1 = e1 * inv;
        if (part == 1) { p0 = tf32f(p0); p1 = tf32f(p1); }
        Ss[i * PS + lane] = p0;
        Ss[i * PS + lane + 32] = p1;
    }
    __syncthreads();

    if (part == 0) {
        for (int idx = tid; idx < 4096; idx += 256) {
            g_A[bh * 4096 + idx] = Ss[(idx >> 6) * PS + (idx & 63)];
        }
        if (tid < 64) {
            float cs = 0.f, rs = 0.f;
            for (int i = 0; i < 64; i++) { cs += Ss[i * PS + tid]; rs += Ss[tid * PS + i]; }
            cbuf[tid] = cs; rbuf[tid] = rs;
        }
        __syncthreads();
        if (tid == 0) {
            float cm = cbuf[0], rm = rbuf[0];
            for (int i = 1; i < 64; i++) { cm = fmaxf(cm, cbuf[i]); rm = fmaxf(rm, rbuf[i]); }
            atomicMax(&g_gmax[0], __float_as_int(cm));
            atomicMax(&g_gmax[1], __float_as_int(rm));
        }
    } else {
        for (int idx = tid; idx < 4096; idx += 256) {
            int j = idx >> 6, d = idx & 63;
            qs[j * PS + d] = tf32f(ldcg(g_v64 + bh * 4096 + idx));
        }
        __syncthreads();
        mmtc<false, false>(ks, Ss, qs, 0.f, 1.0f);
        for (int idx = tid; idx < 4096; idx += 256) {
            g_Bv[bh * 4096 + idx] = ks[(idx >> 6) * PS + (idx & 63)];
        }
    }
}

// ---------------------------------------------------------------------------
// gemm0 body: g_xr @ g_wqkvT -> g_q (Nd=512), frag-order, cp.async 3-stage.
// ---------------------------------------------------------------------------
__device__ void gemm0_body(float* sm, int bx, int by, const float* __restrict__ bias) {
    uint32_t sbase = smem_u32(sm);
    int tid = threadIdx.x, wid = tid >> 5, lane = tid & 31;
    int wmb = (wid >> 2) * 4;
    int wnb = (wid & 3) * 4;
    int grp = lane >> 2, tig = lane & 3;

    const float* Abase = g_xr + (size_t)by * 16 * 4096;
    const float* Bbase = g_wqkvT + (size_t)bx * 16 * 4096;

    float acc[4][4][4];
    #pragma unroll
    for (int mt = 0; mt < 4; mt++)
        #pragma unroll
        for (int nt = 0; nt < 4; nt++)
            #pragma unroll
            for (int r = 0; r < 4; r++) acc[mt][nt][r] = 0.f;

    auto load_chunk = [&](int c, int s) {
        uint32_t a_s = sbase + (uint32_t)(s * 4096) * 4;
        uint32_t b_s = sbase + (uint32_t)((3 + s) * 4096) * 4;
        const float* ag = Abase + c * 4096;
        const float* bg = Bbase + c * 4096;
        #pragma unroll
        for (int i = 0; i < 4; i++) {
            int o = (tid + i * 256) * 4;
            cp16(a_s + o * 4, ag + o);
            cp16(b_s + o * 4, bg + o);
        }
    };

    load_chunk(0, 0); CP_COMMIT();
    load_chunk(1, 1); CP_COMMIT();

    int s = 0;
    for (int c = 0; c < NCHUNK; c++) {
        CP_WAIT(1);
        __syncthreads();
        if (c + 2 < NCHUNK) load_chunk(c + 2, (s + 2) % 3);
        CP_COMMIT();

        const float4* As4 = (const float4*)(sm + s * 4096);
        const float2* Bs2 = (const float2*)(sm + (3 + s) * 4096);

        #pragma unroll
        for (int kk = 0; kk < 4; kk++) {
            float4 af[4]; float2 bf[4];
            #pragma unroll
            for (int mt = 0; mt < 4; mt++)
                af[mt] = As4[((wmb + mt) * 4 + kk) * 32 + lane];
            #pragma unroll
            for (int nt = 0; nt < 4; nt++)
                bf[nt] = Bs2[((wnb + nt) * 4 + kk) * 32 + lane];
            #pragma unroll
            for (int mt = 0; mt < 4; mt++)
                #pragma unroll
                for (int nt = 0; nt < 4; nt++)
                    mma_tf32(acc[mt][nt], (const uint32_t*)&af[mt],
                             (const uint32_t*)&bf[nt], acc[mt][nt]);
        }
        s = (s + 1) % 3;
    }

    #pragma unroll
    for (int mt = 0; mt < 4; mt++) {
        int row0 = by * 128 + (wmb + mt) * 16 + grp;
        #pragma unroll
        for (int nt = 0; nt < 4; nt++) {
            int col0 = bx * 128 + (wnb + nt) * 8 + tig * 2;
            float b0 = bias[col0], b1 = bias[col0 + 1];
            float2 o0 = make_float2(acc[mt][nt][0] + b0, acc[mt][nt][1] + b1);
            float2 o1 = make_float2(acc[mt][nt][2] + b0, acc[mt][nt][3] + b1);
            *(float2*)(g_q + (size_t)row0 * EE + col0) = o0;
            *(float2*)(g_q + (size_t)(row0 + 8) * EE + col0) = o1;
        }
    }
}

// ---------------------------------------------------------------------------
// mega_kernel: grid 176.
//   bids 0..15   : lgemm -> sync0++
//   bids 16..47  : wait sync0==16 -> AB (A softmax+sums || Bv)
//   bids 48..175 : gemm0 (independent; overlaps the chain)
// ---------------------------------------------------------------------------
__global__ __launch_bounds__(256)
void mega_kernel(const float* __restrict__ x, const float* __restrict__ wqkv,
                 const float* __restrict__ bqkv) {
    extern __shared__ float sb[];
    int bid = blockIdx.x, tid = threadIdx.x;

    if (bid < 16) {
        lgemm_body(sb, bid, x, wqkv, bqkv);
        __threadfence();
        __syncthreads();
        if (tid == 0) atomicAdd(&g_sync0, 1);
    } else if (bid < 48) {
        if (tid == 0) { while (*((volatile int*)&g_sync0) != 16) { } }
        __syncthreads();
        int lb = bid - 16;
        ab_body(sb, lb >> 4, lb & 15);
    } else {
        int gb = bid - 48;
        gemm0_body(sb, gb & 3, gb >> 2, bqkv);
    }
}
#define MEGA_SMEM (6 * 4096 * 4)   // 98304 B (gemm0's requirement, max of all)

// ---------------------------------------------------------------------------
// pinv512: 512 threads, grid 16. 6 Newton-Schulz iterations + zB, using the
// 16-warp mmtc512 for ~2x latency hiding on the dependent matmul chain.
// ---------------------------------------------------------------------------
__global__ __launch_bounds__(512)
void pinv512_kernel() {
    extern __shared__ float sm[];
    float* As = sm;
    float* W0 = sm + 1 * PB;
    float* W1 = sm + 2 * PB;
    float* W2 = sm + 3 * PB;
    float* W3 = sm + 4 * PB;

    int bh = blockIdx.x;
    int tid = threadIdx.x;

    float cm = __int_as_float(g_gmax[0]);
    float rm = __int_as_float(g_gmax[1]);
    float inv = 1.0f / (cm * rm);

    for (int idx = tid; idx < 4096; idx += 512) {
        int i = idx >> 6, j = idx & 63;
        As[i * PS + j] = tf32f(g_A[bh * 4096 + idx]);
    }
    __syncthreads();
    for (int idx = tid; idx < 4096; idx += 512) {
        int i = idx >> 6, j = idx & 63;
        W0[i * PS + j] = tf32f(As[j * PS + i] * inv);
    }
    __syncthreads();

    float* z = W0;
    float* x = W1;
    for (int it = 0; it < 6; it++) {
        mmtc512<false, true>(x,  As, z,  0.f,  1.0f);
        mmtc512<true,  true>(W2, x,  x,  7.f,  1.0f);
        mmtc512<true,  true>(W3, x,  W2, 15.f, 1.0f);
        mmtc512<true,  true>(x,  z,  W3, 13.f, 0.25f);
        float* tmp = z; z = x; x = tmp;
    }

    float* Bvs = (z == W0) ? W1 : W0;
    for (int idx = tid; idx < 4096; idx += 512) {
        int i = idx >> 6, j = idx & 63;
        Bvs[i * PS + j] = tf32f(g_Bv[bh * 4096 + idx]);
    }
    __syncthreads();
    mmtc512<false, false>(W3, z, Bvs, 0.f, 1.0f);

    for (int idx = tid; idx < 4096; idx += 512) {
        int i = idx >> 6, j = idx & 63;
        g_zB[bh * 4096 + idx] = W3[i * PS + j];
    }
}
#define PINV_SMEM (5 * PB * 4)   // 87040 B

// ---------------------------------------------------------------------------
// Fused F@zB with tensor cores; writes y in frag-A order (tf32-rounded).
// ---------------------------------------------------------------------------
__global__ __launch_bounds__(256)
void FY_kernel() {
    extern __shared__ float sb[];
    float* ks = sb;
    float* qs = sb + PB;
    float* Ss = sb + 2 * PB;
    int tt = blockIdx.x, bh = blockIdx.y;
    int b = bh / HH, h = bh % HH;
    int tid = threadIdx.x;

    for (int idx = tid; idx < 4096; idx += 256) {
        int j = idx >> 6, d = idx & 63;
        ks[d * PS + j] = tf32f(g_kl[bh * 4096 + idx]);
    }
    for (int idx = tid; idx < 4096; idx += 256) {
        int r = idx >> 6, d = idx & 63;
        qs[r * PS + d] = tf32f(g_q[((size_t)(b * TT + tt * 64 + r)) * EE + h * HD + d] * 0.125f);
    }
    __syncthreads();

    mmtc<false, false>(Ss, qs, ks, 0.f, 1.0f);

    int w = tid / 32, lane = tid % 32;
    for (int r = 0; r < 8; r++) {
        int row = w * 8 + r;
        int t = tt * 64 + row;
        float a0 = Ss[row * PS + lane];
        float a1 = Ss[row * PS + lane + 32];
        if (lane > t) a0 = -INFINITY;
        if (lane + 32 > t) a1 = -INFINITY;
        float mx = fmaxf(a0, a1);
        for (int o = 16; o > 0; o >>= 1) mx = fmaxf(mx, __shfl_xor_sync(0xffffffffu, mx, o));
        float e0 = expf(a0 - mx), e1 = expf(a1 - mx);
        float sm = e0 + e1;
        for (int o = 16; o > 0; o >>= 1) sm += __shfl_xor_sync(0xffffffffu, sm, o);
        float inv = 1.0f / sm;
        Ss[row * PS + lane] = tf32f(e0 * inv);
        Ss[row * PS + lane + 32] = tf32f(e1 * inv);
    }
    __syncthreads();

    for (int idx = tid; idx < 4096; idx += 256) {
        int m = idx >> 6, d = idx & 63;
        ks[m * PS + d] = tf32f(g_zB[bh * 4096 + idx]);
    }
    __syncthreads();

    mmtc<false, false>(qs, Ss, ks, 0.f, 1.0f);

    int rt = (b * TT + tt * 64) >> 7;
    int mb0 = (tt & 1) * 4;
    #pragma unroll
    for (int c_off = 0; c_off < 2; c_off++) {
        int cch = h * 2 + c_off;
        size_t base_f4 = ((size_t)(rt * 16 + cch)) * 1024 + mb0 * 128;
        #pragma unroll
        for (int i = 0; i < 2; i++) {
            int u = tid + i * 256;
            int lane2 = u & 31, kk = (u >> 5) & 3, mbr = u >> 7;
            int grp = lane2 >> 2, tig = lane2 & 3;
            int rl = mbr * 16 + grp;
            int dd = c_off * 32 + kk * 8 + tig;
            float4 o;
            o.x = tf32f(qs[rl * PS + dd]);
            o.y = tf32f(qs[(rl + 8) * PS + dd]);
            o.z = tf32f(qs[rl * PS + dd + 4]);
            o.w = tf32f(qs[(rl + 8) * PS + dd + 4]);
            *(float4*)(g_y + (base_f4 + u) * 4) = o;
        }
    }
}
#define FY_SMEM (3 * PB * 4)

// ---------------------------------------------------------------------------
// gemm1: g_y @ g_wprojT -> out, frag-order, cp.async 3-stage.
// ---------------------------------------------------------------------------
__global__ __launch_bounds__(256)
void gemm1_kernel(const float* __restrict__ bias, float* __restrict__ Cout) {
    extern __shared__ float sm[];
    uint32_t sbase = smem_u32(sm);

    int tid = threadIdx.x, wid = tid >> 5, lane = tid & 31;
    int bx = blockIdx.x, by = blockIdx.y;
    int wmb = (wid >> 2) * 4;
    int wnb = (wid & 3) * 4;
    int grp = lane >> 2, tig = lane & 3;

    const float* Abase = g_y + (size_t)by * 16 * 4096;
    const float* Bbase = g_wprojT + (size_t)bx * 16 * 4096;

    float acc[4][4][4];
    #pragma unroll
    for (int mt = 0; mt < 4; mt++)
        #pragma unroll
        for (int nt = 0; nt < 4; nt++)
            #pragma unroll
            for (int r = 0; r < 4; r++) acc[mt][nt][r] = 0.f;

    auto load_chunk = [&](int c, int s) {
        uint32_t a_s = sbase + (uint32_t)(s * 4096) * 4;
        uint32_t b_s = sbase + (uint32_t)((3 + s) * 4096) * 4;
        const float* ag = Abase + c * 4096;
        const float* bg = Bbase + c * 4096;
        #pragma unroll
        for (int i = 0; i < 4; i++) {
            int o = (tid + i * 256) * 4;
            cp16(a_s + o * 4, ag + o);
            cp16(b_s + o * 4, bg + o);
        }
    };

    load_chunk(0, 0); CP_COMMIT();
    load_chunk(1, 1); CP_COMMIT();

    int s = 0;
    for (int c = 0; c < NCHUNK; c++) {
        CP_WAIT(1);
        __syncthreads();
        if (c + 2 < NCHUNK) load_chunk(c + 2, (s + 2) % 3);
        CP_COMMIT();

        const float4* As4 = (const float4*)(sm + s * 4096);
        const float2* Bs2 = (const float2*)(sm + (3 + s) * 4096);

        #pragma unroll
        for (int kk = 0; kk < 4; kk++) {
            float4 af[4]; float2 bf[4];
            #pragma unroll
            for (int mt = 0; mt < 4; mt++)
                af[mt] = As4[((wmb + mt) * 4 + kk) * 32 + lane];
            #pragma unroll
            for (int nt = 0; nt < 4; nt++)
                bf[nt] = Bs2[((wnb + nt) * 4 + kk) * 32 + lane];
            #pragma unroll
            for (int mt = 0; mt < 4; mt++)
                #pragma unroll
                for (int nt = 0; nt < 4; nt++)
                    mma_tf32(acc[mt][nt], (const uint32_t*)&af[mt],
                             (const uint32_t*)&bf[nt], acc[mt][nt]);
        }
        s = (s + 1) % 3;
    }

    #pragma unroll
    for (int mt = 0; mt < 4; mt++) {
        int row0 = by * 128 + (wmb + mt) * 16 + grp;
        #pragma unroll
        for (int nt = 0; nt < 4; nt++) {
            int col0 = bx * 128 + (wnb + nt) * 8 + tig * 2;
            float b0 = bias[col0], b1 = bias[col0 + 1];
            float2 o0 = make_float2(acc[mt][nt][0] + b0, acc[mt][nt][1] + b1);
            float2 o1 = make_float2(acc[mt][nt][2] + b0, acc[mt][nt][3] + b1);
            *(float2*)(Cout + (size_t)row0 * EE + col0) = o0;
            *(float2*)(Cout + (size_t)(row0 + 8) * EE + col0) = o1;
        }
    }
}
#define GEMM_SMEM (6 * 4096 * 4)

// ---------------------------------------------------------------------------
extern "C" void kernel_launch(void* const* d_in, const int* in_sizes, int n_in,
                              void* d_out, int out_size) {
    const float* x      = (const float*)d_in[0];
    const float* w_qkv  = (const float*)d_in[1];
    const float* b_qkv  = (const float*)d_in[2];
    const float* w_proj = (const float*)d_in[3];
    const float* b_proj = (const float*)d_in[4];
    float* out = (float*)d_out;

    cudaFuncSetAttribute(mega_kernel,
                         cudaFuncAttributeMaxDynamicSharedMemorySize, MEGA_SMEM);
    cudaFuncSetAttribute(pinv512_kernel,
                         cudaFuncAttributeMaxDynamicSharedMemorySize, PINV_SMEM);
    cudaFuncSetAttribute(gemm1_kernel,
                         cudaFuncAttributeMaxDynamicSharedMemorySize, GEMM_SMEM);
    cudaFuncSetAttribute(FY_kernel,
                         cudaFuncAttributeMaxDynamicSharedMemorySize, FY_SMEM);

    // 0. permute+round x (+ xmean), weights; re-arm sync counters
    prep_kernel<<<640, 256>>>(x, w_qkv, w_proj);
    // 1. mega: [lgemm -> AB] chain  ||  gemm0 (q = x@Wq + bq)
    mega_kernel<<<176, 256, MEGA_SMEM>>>(x, w_qkv, b_qkv);
    // 2. pinv + zB (wide 512-thread CTAs for the serial NS chain)
    pinv512_kernel<<<16, 512, PINV_SMEM>>>();
    // 3. y = softmax(q@kl^T) @ zB
    FY_kernel<<<dim3(TT / 64, BH), 256, FY_SMEM>>>();
    // 4. out = y @ w_proj + b_proj
    gemm1_kernel<<<dim3(EE / 128, BB * TT / 128), 256, GEMM_SMEM>>>(b_proj, out);
}

// round 15
// speedup vs baseline: 1.2394x; 1.1282x over previous
#include <cuda_runtime.h>
#include <cuda_bf16.h>
#include <math.h>
#include <stdint.h>

// Problem constants
#define BB 2
#define TT 2048
#define EE 512
#define HH 8
#define HD 64
#define MM 64
#define LL 32
#define BH (BB*HH)
#define NCHUNK 16

// Scratch (device globals; no runtime allocation)
__device__ float g_q[BB*TT*EE];          // q = x@Wq + bq (plain [4096][512])
__device__ float g_xr[BB*TT*EE];         // x in frag-A order, tf32-rounded
__device__ float g_xmean[128*EE];        // group means of x (fp32)
__device__ float g_ql[BH*MM*HD];         // landmark q (scaled 0.125)
__device__ float g_kl[BH*MM*HD];         // landmark k
__device__ float g_k64[BH*MM*HD];        // k rows 0..63 per (b,h)
__device__ float g_v64[BH*MM*HD];        // v rows 0..63 per (b,h)
__device__ float g_A[BH*MM*MM];
__device__ float g_Bv[BH*MM*HD];
__device__ float g_zB[BH*MM*HD];
__device__ float g_y[BB*TT*EE];          // y in frag-A order, tf32-rounded
__device__ float g_wqkvT[EE*EE];         // w_qkv q-cols in frag-B order, rounded
__device__ float g_wprojT[EE*EE];        // w_proj in frag-B order, rounded
__device__ int   g_gmax[2];              // global max col/row sums (float-as-int)
__device__ int   g_sync0;                // chain dependency counter
__device__ int   g_zdone[BH];            // per-bh zB-ready flags

__device__ __forceinline__ uint32_t tf32r(float x) {
    uint32_t r; asm("cvt.rna.tf32.f32 %0, %1;" : "=r"(r) : "f"(x)); return r;
}
__device__ __forceinline__ float tf32f(float x) {
    return __uint_as_float(tf32r(x));
}
__device__ __forceinline__ float ldcg(const float* p) {
    float v; asm volatile("ld.global.cg.f32 %0, [%1];" : "=f"(v) : "l"(p)); return v;
}
__device__ __forceinline__ uint32_t smem_u32(const void* p) {
    uint32_t a;
    asm("{ .reg .u64 t; cvta.to.shared.u64 t, %1; cvt.u32.u64 %0, t; }" : "=r"(a) : "l"(p));
    return a;
}
__device__ __forceinline__ void cp16(uint32_t s, const void* g) {
    asm volatile("cp.async.cg.shared.global [%0], [%1], 16;" :: "r"(s), "l"(g));
}
#define CP_COMMIT() asm volatile("cp.async.commit_group;" ::: "memory")
#define CP_WAIT(n)  asm volatile("cp.async.wait_group %0;" :: "n"(n) : "memory")

__device__ __forceinline__ void mma_tf32(float* d, const uint32_t* a,
                                         const uint32_t* b, const float* c) {
    asm volatile(
        "mma.sync.aligned.m16n8k8.row.col.f32.tf32.tf32.f32 "
        "{%0,%1,%2,%3}, {%4,%5,%6,%7}, {%8,%9}, {%10,%11,%12,%13};"
        : "=f"(d[0]), "=f"(d[1]), "=f"(d[2]), "=f"(d[3])
        : "r"(a[0]), "r"(a[1]), "r"(a[2]), "r"(a[3]),
          "r"(b[0]), "r"(b[1]),
          "f"(c[0]), "f"(c[1]), "f"(c[2]), "f"(c[3]));
}

// ---------------------------------------------------------------------------
// prep_kernel: x -> frag-A + xmean; weights -> frag-B; re-arm sync globals.
// ---------------------------------------------------------------------------
__global__ __launch_bounds__(256)
void prep_kernel(const float* __restrict__ x, const float* __restrict__ wqkv,
                 const float* __restrict__ wproj) {
    __shared__ float t[128 * 36];   // >= 32*132
    int bid = blockIdx.x, tid = threadIdx.x;
    if (bid == 0) {
        if (tid == 0) { g_gmax[0] = 0; g_gmax[1] = 0; g_sync0 = 0; }
        if (tid < BH) g_zdone[tid] = 0;
    }
    if (bid < 512) {
        int ch = bid, rt = ch >> 4, c = ch & 15;
        #pragma unroll
        for (int i = 0; i < 4; i++) {
            int s = tid + i * 256, r = s >> 3, c4 = (s & 7) * 4;
            float4 v = *(const float4*)(x + (size_t)(rt * 128 + r) * 512 + c * 32 + c4);
            t[r * 36 + c4] = v.x; t[r * 36 + c4 + 1] = v.y;
            t[r * 36 + c4 + 2] = v.z; t[r * 36 + c4 + 3] = v.w;
        }
        __syncthreads();
        #pragma unroll
        for (int i = 0; i < 4; i++) {
            int f = tid + i * 256;
            int lane = f & 31, kk = (f >> 5) & 3, mb = f >> 7;
            int grp = lane >> 2, tig = lane & 3;
            int rr = mb * 16 + grp, cc = kk * 8 + tig;
            float4 o;
            o.x = tf32f(t[rr * 36 + cc]);
            o.y = tf32f(t[(rr + 8) * 36 + cc]);
            o.z = tf32f(t[rr * 36 + cc + 4]);
            o.w = tf32f(t[(rr + 8) * 36 + cc + 4]);
            *(float4*)(g_xr + (size_t)ch * 4096 + f * 4) = o;
        }
        if (tid < 128) {
            int gr = tid >> 5, cc = tid & 31;
            float s = 0.f;
            #pragma unroll 8
            for (int i = 0; i < 32; i++) s += t[(gr * 32 + i) * 36 + cc];
            g_xmean[(rt * 4 + gr) * 512 + c * 32 + cc] = s * (1.0f / 32.0f);
        }
    } else {
        const float* w; float* dst; int N, ch;
        if (bid < 576) { w = wqkv; dst = g_wqkvT; N = 1536; ch = bid - 512; }
        else           { w = wproj; dst = g_wprojT; N = 512;  ch = bid - 576; }
        int ntile = ch >> 4, c = ch & 15;
        #pragma unroll
        for (int i = 0; i < 4; i++) {
            int s = tid + i * 256, kr = s >> 5, n4 = (s & 31) * 4;
            float4 v = *(const float4*)(w + (size_t)(c * 32 + kr) * N + ntile * 128 + n4);
            t[kr * 132 + n4] = v.x; t[kr * 132 + n4 + 1] = v.y;
            t[kr * 132 + n4 + 2] = v.z; t[kr * 132 + n4 + 3] = v.w;
        }
        __syncthreads();
        #pragma unroll
        for (int i = 0; i < 8; i++) {
            int f = tid + i * 256;
            int lane = f & 31, kk = (f >> 5) & 3, nb = f >> 7;
            int grp = lane >> 2, tig = lane & 3;
            int nn = nb * 8 + grp, kx = kk * 8 + tig;
            float2 o;
            o.x = tf32f(t[kx * 132 + nn]);
            o.y = tf32f(t[(kx + 4) * 132 + nn]);
            *(float2*)(dst + (size_t)ch * 4096 + f * 2) = o;
        }
    }
}

// ---------------------------------------------------------------------------
// Tensor-core 64x64 matmul on PS-padded smem, 256 threads (8 warps).
// ---------------------------------------------------------------------------
#define PS 68
#define PB (64 * PS)

template<bool NEG, bool RNDOUT>
__device__ __forceinline__ void mmtc(float* __restrict__ C,
                                     const float* __restrict__ L,
                                     const float* __restrict__ R,
                                     float dc, float scale) {
    int wid = threadIdx.x >> 5, lane = threadIdx.x & 31;
    int grp = lane >> 2, tig = lane & 3;
    int m0 = (wid & 3) * 16, n0 = (wid >> 2) * 32;

    float acc[4][4];
    #pragma unroll
    for (int nt = 0; nt < 4; nt++)
        #pragma unroll
        for (int r = 0; r < 4; r++) acc[nt][r] = 0.f;

    #pragma unroll
    for (int kk = 0; kk < 64; kk += 8) {
        uint32_t a[4];
        a[0] = __float_as_uint(L[(m0 + grp) * PS + kk + tig]);
        a[1] = __float_as_uint(L[(m0 + grp + 8) * PS + kk + tig]);
        a[2] = __float_as_uint(L[(m0 + grp) * PS + kk + tig + 4]);
        a[3] = __float_as_uint(L[(m0 + grp + 8) * PS + kk + tig + 4]);
        #pragma unroll
        for (int nt = 0; nt < 4; nt++) {
            int n = n0 + nt * 8 + grp;
            float b0v = R[(kk + tig) * PS + n];
            float b1v = R[(kk + tig + 4) * PS + n];
            uint32_t b[2];
            if (NEG) {
                b0v = ((kk + tig) == n ? dc : 0.f) - b0v;
                b1v = ((kk + tig + 4) == n ? dc : 0.f) - b1v;
                b[0] = tf32r(b0v);
                b[1] = tf32r(b1v);
            } else {
                b[0] = __float_as_uint(b0v);
                b[1] = __float_as_uint(b1v);
            }
            mma_tf32(acc[nt], a, b, acc[nt]);
        }
    }

    #pragma unroll
    for (int nt = 0; nt < 4; nt++) {
        int c0 = n0 + nt * 8 + tig * 2;
        float o0 = acc[nt][0] * scale, o1 = acc[nt][1] * scale;
        float o2 = acc[nt][2] * scale, o3 = acc[nt][3] * scale;
        if (RNDOUT) { o0 = tf32f(o0); o1 = tf32f(o1); o2 = tf32f(o2); o3 = tf32f(o3); }
        C[(m0 + grp) * PS + c0]         = o0;
        C[(m0 + grp) * PS + c0 + 1]     = o1;
        C[(m0 + grp + 8) * PS + c0]     = o2;
        C[(m0 + grp + 8) * PS + c0 + 1] = o3;
    }
    __syncthreads();
}

// ---------------------------------------------------------------------------
// Wide 64x64 matmul: 512 threads (16 warps), each warp 16x16 (NS chain).
// ---------------------------------------------------------------------------
template<bool NEG, bool RNDOUT>
__device__ __forceinline__ void mmtc512(float* __restrict__ C,
                                        const float* __restrict__ L,
                                        const float* __restrict__ R,
                                        float dc, float scale) {
    int wid = threadIdx.x >> 5, lane = threadIdx.x & 31;
    int grp = lane >> 2, tig = lane & 3;
    int m0 = (wid & 3) * 16, n0 = (wid >> 2) * 16;

    float acc[2][4];
    #pragma unroll
    for (int nt = 0; nt < 2; nt++)
        #pragma unroll
        for (int r = 0; r < 4; r++) acc[nt][r] = 0.f;

    #pragma unroll
    for (int kk = 0; kk < 64; kk += 8) {
        uint32_t a[4];
        a[0] = __float_as_uint(L[(m0 + grp) * PS + kk + tig]);
        a[1] = __float_as_uint(L[(m0 + grp + 8) * PS + kk + tig]);
        a[2] = __float_as_uint(L[(m0 + grp) * PS + kk + tig + 4]);
        a[3] = __float_as_uint(L[(m0 + grp + 8) * PS + kk + tig + 4]);
        #pragma unroll
        for (int nt = 0; nt < 2; nt++) {
            int n = n0 + nt * 8 + grp;
            float b0v = R[(kk + tig) * PS + n];
            float b1v = R[(kk + tig + 4) * PS + n];
            uint32_t b[2];
            if (NEG) {
                b0v = ((kk + tig) == n ? dc : 0.f) - b0v;
                b1v = ((kk + tig + 4) == n ? dc : 0.f) - b1v;
                b[0] = tf32r(b0v);
                b[1] = tf32r(b1v);
            } else {
                b[0] = __float_as_uint(b0v);
                b[1] = __float_as_uint(b1v);
            }
            mma_tf32(acc[nt], a, b, acc[nt]);
        }
    }

    #pragma unroll
    for (int nt = 0; nt < 2; nt++) {
        int c0 = n0 + nt * 8 + tig * 2;
        float o0 = acc[nt][0] * scale, o1 = acc[nt][1] * scale;
        float o2 = acc[nt][2] * scale, o3 = acc[nt][3] * scale;
        if (RNDOUT) { o0 = tf32f(o0); o1 = tf32f(o1); o2 = tf32f(o2); o3 = tf32f(o3); }
        C[(m0 + grp) * PS + c0]         = o0;
        C[(m0 + grp) * PS + c0 + 1]     = o1;
        C[(m0 + grp + 8) * PS + c0]     = o2;
        C[(m0 + grp + 8) * PS + c0 + 1] = o3;
    }
    __syncthreads();
}

// ---------------------------------------------------------------------------
// 128x64 matmul: 512 threads (16 warps), each warp 16 rows x 32 cols.
// C[128xPS] = L[128xPS] @ R[64xPS ([k][n])].
// ---------------------------------------------------------------------------
__device__ __forceinline__ void mmtc128(float* __restrict__ C,
                                        const float* __restrict__ L,
                                        const float* __restrict__ R) {
    int wid = threadIdx.x >> 5, lane = threadIdx.x & 31;
    int grp = lane >> 2, tig = lane & 3;
    int m0 = (wid & 7) * 16, n0 = (wid >> 3) * 32;

    float acc[4][4];
    #pragma unroll
    for (int nt = 0; nt < 4; nt++)
        #pragma unroll
        for (int r = 0; r < 4; r++) acc[nt][r] = 0.f;

    #pragma unroll
    for (int kk = 0; kk < 64; kk += 8) {
        uint32_t a[4];
        a[0] = __float_as_uint(L[(m0 + grp) * PS + kk + tig]);
        a[1] = __float_as_uint(L[(m0 + grp + 8) * PS + kk + tig]);
        a[2] = __float_as_uint(L[(m0 + grp) * PS + kk + tig + 4]);
        a[3] = __float_as_uint(L[(m0 + grp + 8) * PS + kk + tig + 4]);
        #pragma unroll
        for (int nt = 0; nt < 4; nt++) {
            int n = n0 + nt * 8 + grp;
            uint32_t b[2];
            b[0] = __float_as_uint(R[(kk + tig) * PS + n]);
            b[1] = __float_as_uint(R[(kk + tig + 4) * PS + n]);
            mma_tf32(acc[nt], a, b, acc[nt]);
        }
    }

    #pragma unroll
    for (int nt = 0; nt < 4; nt++) {
        int c0 = n0 + nt * 8 + tig * 2;
        C[(m0 + grp) * PS + c0]         = acc[nt][0];
        C[(m0 + grp) * PS + c0 + 1]     = acc[nt][1];
        C[(m0 + grp + 8) * PS + c0]     = acc[nt][2];
        C[(m0 + grp + 8) * PS + c0 + 1] = acc[nt][3];
    }
    __syncthreads();
}

// ---------------------------------------------------------------------------
// lgemm body (in mega): part 0 -> ql/kl from xmean; part 1 -> k64/v64.
// ---------------------------------------------------------------------------
__device__ void lgemm_body(float* sb, int bid, const float* __restrict__ x,
                           const float* __restrict__ wqkv,
                           const float* __restrict__ bqkv) {
    float* As = sb;
    float* Bt = sb + 4608;
    int tid = threadIdx.x;
    int part = bid >> 3, ntb = bid & 7;
    int wid = tid >> 5, lane = tid & 31;
    int wm = (wid >> 2) * 64, wn = (wid & 3) * 32;
    int grp = lane >> 2, tig = lane & 3;
    int nbase = part ? (512 + ntb * 128) : (ntb * 128);

    float acc[4][4][4] = {};

    for (int k0 = 0; k0 < 512; k0 += 32) {
        #pragma unroll
        for (int i = 0; i < 4; i++) {
            int s = tid + i * 256, r = s >> 3, c4 = (s & 7) * 4;
            const float* arow;
            if (part == 0) arow = g_xmean + (size_t)r * 512;
            else           arow = x + ((size_t)((r >> 6) * TT + (r & 63))) * 512;
            float4 v = *(const float4*)(arow + k0 + c4);
            As[r * 36 + c4]     = tf32f(v.x);
            As[r * 36 + c4 + 1] = tf32f(v.y);
            As[r * 36 + c4 + 2] = tf32f(v.z);
            As[r * 36 + c4 + 3] = tf32f(v.w);
        }
        #pragma unroll
        for (int i = 0; i < 4; i++) {
            int s = tid + i * 256, kr = s >> 5, n4 = (s & 31) * 4;
            float4 v = *(const float4*)(wqkv + (size_t)(k0 + kr) * 1536 + nbase + n4);
            Bt[kr * 132 + n4]     = tf32f(v.x);
            Bt[kr * 132 + n4 + 1] = tf32f(v.y);
            Bt[kr * 132 + n4 + 2] = tf32f(v.z);
            Bt[kr * 132 + n4 + 3] = tf32f(v.w);
        }
        __syncthreads();

        #pragma unroll
        for (int kk = 0; kk < 32; kk += 8) {
            uint32_t af[4][4], bf[4][2];
            #pragma unroll
            for (int mt = 0; mt < 4; mt++) {
                int m = wm + mt * 16;
                af[mt][0] = __float_as_uint(As[(m + grp) * 36 + kk + tig]);
                af[mt][1] = __float_as_uint(As[(m + grp + 8) * 36 + kk + tig]);
                af[mt][2] = __float_as_uint(As[(m + grp) * 36 + kk + tig + 4]);
                af[mt][3] = __float_as_uint(As[(m + grp + 8) * 36 + kk + tig + 4]);
            }
            #pragma unroll
            for (int nt = 0; nt < 4; nt++) {
                int n = wn + nt * 8 + grp;
                bf[nt][0] = __float_as_uint(Bt[(kk + tig) * 132 + n]);
                bf[nt][1] = __float_as_uint(Bt[(kk + tig + 4) * 132 + n]);
            }
            #pragma unroll
            for (int mt = 0; mt < 4; mt++)
                #pragma unroll
                for (int nt = 0; nt < 4; nt++)
                    mma_tf32(acc[mt][nt], af[mt], bf[nt], acc[mt][nt]);
        }
        __syncthreads();
    }

    #pragma unroll
    for (int mt = 0; mt < 4; mt++) {
        int row0 = wm + mt * 16 + grp;
        #pragma unroll
        for (int nt = 0; nt < 4; nt++) {
            int nloc0 = ntb * 128 + wn + nt * 8 + tig * 2;
            #pragma unroll
            for (int q = 0; q < 4; q++) {
                int row = row0 + (q >> 1) * 8;
                int nloc = nloc0 + (q & 1);
                float val = acc[mt][nt][q] + bqkv[(part ? 512 : 0) + nloc];
                int b = row >> 6, mj = row & 63;
                int h = nloc >> 6, d = nloc & 63;
                if (part == 0) {
                    if (h < 8) g_ql[((b * 8 + h) * 64 + mj) * 64 + d] = val * 0.125f;
                    else       g_kl[((b * 8 + h - 8) * 64 + mj) * 64 + d] = val;
                } else {
                    if (h < 8) g_k64[((b * 8 + h) * 64 + mj) * 64 + d] = val;
                    else       g_v64[((b * 8 + h - 8) * 64 + mj) * 64 + d] = val;
                }
            }
        }
    }
}

// ---------------------------------------------------------------------------
// AB body (in mega): part 0 -> A softmax + sum maxima; part 1 -> Bv.
// ---------------------------------------------------------------------------
__device__ void ab_body(float* sb, int part, int bh) {
    float* qs = sb;
    float* ks = sb + PB;
    float* Ss = sb + 2 * PB;
    float* cbuf = sb + 3 * PB;
    float* rbuf = cbuf + 64;
    int tid = threadIdx.x;

    for (int idx = tid; idx < 4096; idx += 256) {
        qs[(idx >> 6) * PS + (idx & 63)] = tf32f(ldcg(g_ql + bh * 4096 + idx));
    }
    const float* kn = (part == 0) ? g_kl : g_k64;
    for (int idx = tid; idx < 4096; idx += 256) {
        int j = idx >> 6, d = idx & 63;
        ks[d * PS + j] = tf32f(ldcg(kn + bh * 4096 + idx));
    }
    __syncthreads();

    mmtc<false, false>(Ss, qs, ks, 0.f, 1.0f);

    int w = tid / 32, lane = tid % 32;
    for (int r = 0; r < 8; r++) {
        int i = w * 8 + r;
        float a0 = Ss[i * PS + lane];
        float a1 = Ss[i * PS + lane + 32];
        if (lane > i) a0 = -INFINITY;
        if (lane + 32 > i) a1 = -INFINITY;
        float mx = fmaxf(a0, a1);
        for (int o = 16; o > 0; o >>= 1) mx = fmaxf(mx, __shfl_xor_sync(0xffffffffu, mx, o));
        float e0 = expf(a0 - mx), e1 = expf(a1 - mx);
        float sm = e0 + e1;
        for (int o = 16; o > 0; o >>= 1) sm += __shfl_xor_sync(0xffffffffu, sm, o);
        float inv = 1.0f / sm;
        float p0 = e0 * inv, p1 = e1 * inv;
        if (part == 1) { p0 = tf32f(p0); p1 = tf32f(p1); }
        Ss[i * PS + lane] = p0;
        Ss[i * PS + lane + 32] = p1;
    }
    __syncthreads();

    if (part == 0) {
        for (int idx = tid; idx < 4096; idx += 256) {
            g_A[bh * 4096 + idx] = Ss[(idx >> 6) * PS + (idx & 63)];
        }
        if (tid < 64) {
            float cs = 0.f, rs = 0.f;
            for (int i = 0; i < 64; i++) { cs += Ss[i * PS + tid]; rs += Ss[tid * PS + i]; }
            cbuf[tid] = cs; rbuf[tid] = rs;
        }
        __syncthreads();
        if (tid == 0) {
            float cm = cbuf[0], rm = rbuf[0];
            for (int i = 1; i < 64; i++) { cm = fmaxf(cm, cbuf[i]); rm = fmaxf(rm, rbuf[i]); }
            atomicMax(&g_gmax[0], __float_as_int(cm));
            atomicMax(&g_gmax[1], __float_as_int(rm));
        }
    } else {
        for (int idx = tid; idx < 4096; idx += 256) {
            int j = idx >> 6, d = idx & 63;
            qs[j * PS + d] = tf32f(ldcg(g_v64 + bh * 4096 + idx));
        }
        __syncthreads();
        mmtc<false, false>(ks, Ss, qs, 0.f, 1.0f);
        for (int idx = tid; idx < 4096; idx += 256) {
            g_Bv[bh * 4096 + idx] = ks[(idx >> 6) * PS + (idx & 63)];
        }
    }
}

// ---------------------------------------------------------------------------
// gemm0 body (in mega): g_xr @ g_wqkvT -> g_q, frag-order, cp.async 3-stage.
// ---------------------------------------------------------------------------
__device__ void gemm0_body(float* sm, int bx, int by, const float* __restrict__ bias) {
    uint32_t sbase = smem_u32(sm);
    int tid = threadIdx.x, wid = tid >> 5, lane = tid & 31;
    int wmb = (wid >> 2) * 4;
    int wnb = (wid & 3) * 4;
    int grp = lane >> 2, tig = lane & 3;

    const float* Abase = g_xr + (size_t)by * 16 * 4096;
    const float* Bbase = g_wqkvT + (size_t)bx * 16 * 4096;

    float acc[4][4][4];
    #pragma unroll
    for (int mt = 0; mt < 4; mt++)
        #pragma unroll
        for (int nt = 0; nt < 4; nt++)
            #pragma unroll
            for (int r = 0; r < 4; r++) acc[mt][nt][r] = 0.f;

    auto load_chunk = [&](int c, int s) {
        uint32_t a_s = sbase + (uint32_t)(s * 4096) * 4;
        uint32_t b_s = sbase + (uint32_t)((3 + s) * 4096) * 4;
        const float* ag = Abase + c * 4096;
        const float* bg = Bbase + c * 4096;
        #pragma unroll
        for (int i = 0; i < 4; i++) {
            int o = (tid + i * 256) * 4;
            cp16(a_s + o * 4, ag + o);
            cp16(b_s + o * 4, bg + o);
        }
    };

    load_chunk(0, 0); CP_COMMIT();
    load_chunk(1, 1); CP_COMMIT();

    int s = 0;
    for (int c = 0; c < NCHUNK; c++) {
        CP_WAIT(1);
        __syncthreads();
        if (c + 2 < NCHUNK) load_chunk(c + 2, (s + 2) % 3);
        CP_COMMIT();

        const float4* As4 = (const float4*)(sm + s * 4096);
        const float2* Bs2 = (const float2*)(sm + (3 + s) * 4096);

        #pragma unroll
        for (int kk = 0; kk < 4; kk++) {
            float4 af[4]; float2 bf[4];
            #pragma unroll
            for (int mt = 0; mt < 4; mt++)
                af[mt] = As4[((wmb + mt) * 4 + kk) * 32 + lane];
            #pragma unroll
            for (int nt = 0; nt < 4; nt++)
                bf[nt] = Bs2[((wnb + nt) * 4 + kk) * 32 + lane];
            #pragma unroll
            for (int mt = 0; mt < 4; mt++)
                #pragma unroll
                for (int nt = 0; nt < 4; nt++)
                    mma_tf32(acc[mt][nt], (const uint32_t*)&af[mt],
                             (const uint32_t*)&bf[nt], acc[mt][nt]);
        }
        s = (s + 1) % 3;
    }

    #pragma unroll
    for (int mt = 0; mt < 4; mt++) {
        int row0 = by * 128 + (wmb + mt) * 16 + grp;
        #pragma unroll
        for (int nt = 0; nt < 4; nt++) {
            int col0 = bx * 128 + (wnb + nt) * 8 + tig * 2;
            float b0 = bias[col0], b1 = bias[col0 + 1];
            float2 o0 = make_float2(acc[mt][nt][0] + b0, acc[mt][nt][1] + b1);
            float2 o1 = make_float2(acc[mt][nt][2] + b0, acc[mt][nt][3] + b1);
            *(float2*)(g_q + (size_t)row0 * EE + col0) = o0;
            *(float2*)(g_q + (size_t)(row0 + 8) * EE + col0) = o1;
        }
    }
}

// ---------------------------------------------------------------------------
// mega_kernel: grid 176.
//   bids 0..15   : lgemm -> sync0++
//   bids 16..47  : wait sync0==16 -> AB
//   bids 48..175 : gemm0 (independent; overlaps the chain)
// ---------------------------------------------------------------------------
__global__ __launch_bounds__(256)
void mega_kernel(const float* __restrict__ x, const float* __restrict__ wqkv,
                 const float* __restrict__ bqkv) {
    extern __shared__ float sb[];
    int bid = blockIdx.x, tid = threadIdx.x;

    if (bid < 16) {
        lgemm_body(sb, bid, x, wqkv, bqkv);
        __threadfence();
        __syncthreads();
        if (tid == 0) atomicAdd(&g_sync0, 1);
    } else if (bid < 48) {
        if (tid == 0) { while (*((volatile int*)&g_sync0) != 16) { } }
        __syncthreads();
        int lb = bid - 16;
        ab_body(sb, lb >> 4, lb & 15);
    } else {
        int gb = bid - 48;
        gemm0_body(sb, gb & 3, gb >> 2, bqkv);
    }
}
#define MEGA_SMEM (6 * 4096 * 4)   // 98304 B

// ---------------------------------------------------------------------------
// PFY kernel: grid 272, 512 threads.
//   bids 0..15   : pinv (NS chain + zB) -> g_zdone[bh] = 1
//   bids 16..271 : FY 128-row tiles; phase-1 (S + softmax) overlaps pinv,
//                  phase-2 waits on g_zdone[bh].
// ---------------------------------------------------------------------------
__global__ __launch_bounds__(512)
void PFY_kernel() {
    extern __shared__ float sb[];
    int bid = blockIdx.x, tid = threadIdx.x;

    if (bid < 16) {
        // ---- pinv body (512 threads, mmtc512) ----
        float* As = sb;
        float* W0 = sb + 1 * PB;
        float* W1 = sb + 2 * PB;
        float* W2 = sb + 3 * PB;
        float* W3 = sb + 4 * PB;
        int bh = bid;

        float cm = __int_as_float(g_gmax[0]);
        float rm = __int_as_float(g_gmax[1]);
        float inv = 1.0f / (cm * rm);

        for (int idx = tid; idx < 4096; idx += 512) {
            int i = idx >> 6, j = idx & 63;
            As[i * PS + j] = tf32f(g_A[bh * 4096 + idx]);
        }
        __syncthreads();
        for (int idx = tid; idx < 4096; idx += 512) {
            int i = idx >> 6, j = idx & 63;
            W0[i * PS + j] = tf32f(As[j * PS + i] * inv);
        }
        __syncthreads();

        float* z = W0;
        float* x = W1;
        for (int it = 0; it < 6; it++) {
            mmtc512<false, true>(x,  As, z,  0.f,  1.0f);
            mmtc512<true,  true>(W2, x,  x,  7.f,  1.0f);
            mmtc512<true,  true>(W3, x,  W2, 15.f, 1.0f);
            mmtc512<true,  true>(x,  z,  W3, 13.f, 0.25f);
            float* tmp = z; z = x; x = tmp;
        }

        float* Bvs = (z == W0) ? W1 : W0;
        for (int idx = tid; idx < 4096; idx += 512) {
            int i = idx >> 6, j = idx & 63;
            Bvs[i * PS + j] = tf32f(g_Bv[bh * 4096 + idx]);
        }
        __syncthreads();
        mmtc512<false, false>(W3, z, Bvs, 0.f, 1.0f);

        for (int idx = tid; idx < 4096; idx += 512) {
            int i = idx >> 6, j = idx & 63;
            g_zB[bh * 4096 + idx] = W3[i * PS + j];
        }
        __threadfence();
        __syncthreads();
        if (tid == 0) atomicExch(&g_zdone[bh], 1);
    } else {
        // ---- FY body: 128-row tile (tt2), 512 threads ----
        float* ks  = sb;               // kl^T [d][j] (PB); later zB [m][d]
        float* qs  = sb + PB;          // q 128 rows (2 PB); later Y
        float* Ss  = sb + 3 * PB;      // S / F 128 rows (2 PB)
        int fb = bid - 16;
        int tt2 = fb & 15, bh = fb >> 4;
        int b = bh / HH, h = bh % HH;

        for (int idx = tid; idx < 4096; idx += 512) {
            int j = idx >> 6, d = idx & 63;
            ks[d * PS + j] = tf32f(g_kl[bh * 4096 + idx]);
        }
        for (int idx = tid; idx < 8192; idx += 512) {
            int r = idx >> 6, d = idx & 63;
            qs[r * PS + d] = tf32f(g_q[((size_t)(b * TT + tt2 * 128 + r)) * EE + h * HD + d] * 0.125f);
        }
        __syncthreads();

        mmtc128(Ss, qs, ks);   // S = q @ kl^T  (128x64)

        int w = tid / 32, lane = tid % 32;
        for (int r = 0; r < 8; r++) {
            int row = w * 8 + r;
            int t = tt2 * 128 + row;
            float a0 = Ss[row * PS + lane];
            float a1 = Ss[row * PS + lane + 32];
            if (lane > t) a0 = -INFINITY;
            if (lane + 32 > t) a1 = -INFINITY;
            float mx = fmaxf(a0, a1);
            for (int o = 16; o > 0; o >>= 1) mx = fmaxf(mx, __shfl_xor_sync(0xffffffffu, mx, o));
            float e0 = expf(a0 - mx), e1 = expf(a1 - mx);
            float sm = e0 + e1;
            for (int o = 16; o > 0; o >>= 1) sm += __shfl_xor_sync(0xffffffffu, sm, o);
            float inv = 1.0f / sm;
            Ss[row * PS + lane] = tf32f(e0 * inv);
            Ss[row * PS + lane + 32] = tf32f(e1 * inv);
        }
        __syncthreads();

        // wait for zB of this bh, then load it over ks
        if (tid == 0) { while (*((volatile int*)&g_zdone[bh]) == 0) { } }
        __syncthreads();
        for (int idx = tid; idx < 4096; idx += 512) {
            int m = idx >> 6, d = idx & 63;
            ks[m * PS + d] = tf32f(ldcg(g_zB + bh * 4096 + idx));
        }
        __syncthreads();

        mmtc128(qs, Ss, ks);   // Y = F @ zB  (128x64) -> qs

        // writeback: this block covers frag-A chunks rt*16 + h*2 + {0,1} fully
        int rt = (b * 16) + tt2;   // (b*TT + tt2*128) / 128
        #pragma unroll
        for (int c_off = 0; c_off < 2; c_off++) {
            int cch = h * 2 + c_off;
            size_t base_f4 = ((size_t)(rt * 16 + cch)) * 1024;
            #pragma unroll
            for (int i = 0; i < 2; i++) {
                int u = tid + i * 512;
                int lane2 = u & 31, kk = (u >> 5) & 3, mbr = u >> 7;
                int grp = lane2 >> 2, tig = lane2 & 3;
                int rl = mbr * 16 + grp;
                int dd = c_off * 32 + kk * 8 + tig;
                float4 o;
                o.x = tf32f(qs[rl * PS + dd]);
                o.y = tf32f(qs[(rl + 8) * PS + dd]);
                o.z = tf32f(qs[rl * PS + dd + 4]);
                o.w = tf32f(qs[(rl + 8) * PS + dd + 4]);
                *(float4*)(g_y + (base_f4 + u) * 4) = o;
            }
        }
    }
}
#define PFY_SMEM (5 * PB * 4 > 5 * PB * 4 ? 5 * PB * 4 : 5 * PB * 4)
#undef PFY_SMEM
#define PFY_SMEM (5 * PB * 4 + 0 * 4)   // pinv: 5 PB; FY: 5 PB -> 87040 B

// ---------------------------------------------------------------------------
// gemm1: g_y @ g_wprojT -> out, frag-order, cp.async 3-stage.
// ---------------------------------------------------------------------------
__global__ __launch_bounds__(256)
void gemm1_kernel(const float* __restrict__ bias, float* __restrict__ Cout) {
    extern __shared__ float sm[];
    uint32_t sbase = smem_u32(sm);

    int tid = threadIdx.x, wid = tid >> 5, lane = tid & 31;
    int bx = blockIdx.x, by = blockIdx.y;
    int wmb = (wid >> 2) * 4;
    int wnb = (wid & 3) * 4;
    int grp = lane >> 2, tig = lane & 3;

    const float* Abase = g_y + (size_t)by * 16 * 4096;
    const float* Bbase = g_wprojT + (size_t)bx * 16 * 4096;

    float acc[4][4][4];
    #pragma unroll
    for (int mt = 0; mt < 4; mt++)
        #pragma unroll
        for (int nt = 0; nt < 4; nt++)
            #pragma unroll
            for (int r = 0; r < 4; r++) acc[mt][nt][r] = 0.f;

    auto load_chunk = [&](int c, int s) {
        uint32_t a_s = sbase + (uint32_t)(s * 4096) * 4;
        uint32_t b_s = sbase + (uint32_t)((3 + s) * 4096) * 4;
        const float* ag = Abase + c * 4096;
        const float* bg = Bbase + c * 4096;
        #pragma unroll
        for (int i = 0; i < 4; i++) {
            int o = (tid + i * 256) * 4;
            cp16(a_s + o * 4, ag + o);
            cp16(b_s + o * 4, bg + o);
        }
    };

    load_chunk(0, 0); CP_COMMIT();
    load_chunk(1, 1); CP_COMMIT();

    int s = 0;
    for (int c = 0; c < NCHUNK; c++) {
        CP_WAIT(1);
        __syncthreads();
        if (c + 2 < NCHUNK) load_chunk(c + 2, (s + 2) % 3);
        CP_COMMIT();

        const float4* As4 = (const float4*)(sm + s * 4096);
        const float2* Bs2 = (const float2*)(sm + (3 + s) * 4096);

        #pragma unroll
        for (int kk = 0; kk < 4; kk++) {
            float4 af[4]; float2 bf[4];
            #pragma unroll
            for (int mt = 0; mt < 4; mt++)
                af[mt] = As4[((wmb + mt) * 4 + kk) * 32 + lane];
            #pragma unroll
            for (int nt = 0; nt < 4; nt++)
                bf[nt] = Bs2[((wnb + nt) * 4 + kk) * 32 + lane];
            #pragma unroll
            for (int mt = 0; mt < 4; mt++)
                #pragma unroll
                for (int nt = 0; nt < 4; nt++)
                    mma_tf32(acc[mt][nt], (const uint32_t*)&af[mt],
                             (const uint32_t*)&bf[nt], acc[mt][nt]);
        }
        s = (s + 1) % 3;
    }

    #pragma unroll
    for (int mt = 0; mt < 4; mt++) {
        int row0 = by * 128 + (wmb + mt) * 16 + grp;
        #pragma unroll
        for (int nt = 0; nt < 4; nt++) {
            int col0 = bx * 128 + (wnb + nt) * 8 + tig * 2;
            float b0 = bias[col0], b1 = bias[col0 + 1];
            float2 o0 = make_float2(acc[mt][nt][0] + b0, acc[mt][nt][1] + b1);
            float2 o1 = make_float2(acc[mt][nt][2] + b0, acc[mt][nt][3] + b1);
            *(float2*)(Cout + (size_t)row0 * EE + col0) = o0;
            *(float2*)(Cout + (size_t)(row0 + 8) * EE + col0) = o1;
        }
    }
}
#define GEMM_SMEM (6 * 4096 * 4)

// ---------------------------------------------------------------------------
extern "C" void kernel_launch(void* const* d_in, const int* in_sizes, int n_in,
                              void* d_out, int out_size) {
    const float* x      = (const float*)d_in[0];
    const float* w_qkv  = (const float*)d_in[1];
    const float* b_qkv  = (const float*)d_in[2];
    const float* w_proj = (const float*)d_in[3];
    const float* b_proj = (const float*)d_in[4];
    float* out = (float*)d_out;

    cudaFuncSetAttribute(mega_kernel,
                         cudaFuncAttributeMaxDynamicSharedMemorySize, MEGA_SMEM);
    cudaFuncSetAttribute(PFY_kernel,
                         cudaFuncAttributeMaxDynamicSharedMemorySize, PFY_SMEM);
    cudaFuncSetAttribute(gemm1_kernel,
                         cudaFuncAttributeMaxDynamicSharedMemorySize, GEMM_SMEM);

    // 0. permute+round x (+ xmean), weights; re-arm sync globals
    prep_kernel<<<640, 256>>>(x, w_qkv, w_proj);
    // 1. mega: [lgemm -> AB] chain  ||  gemm0 (q = x@Wq + bq)
    mega_kernel<<<176, 256, MEGA_SMEM>>>(x, w_qkv, b_qkv);
    // 2. PFY: pinv+zB  ||  FY (phase-1 overlaps pinv; phase-2 waits per-bh)
    PFY_kernel<<<272, 512, PFY_SMEM>>>();
    // 3. out = y @ w_proj + b_proj
    gemm1_kernel<<<dim3(EE / 128, BB * TT / 128), 256, GEMM_SMEM>>>(b_proj, out);
}